// round 5
// baseline (speedup 1.0000x reference)
#include <cuda_runtime.h>
#include <cuda_bf16.h>
#include <cstdint>

// Problem constants (from reference): T=2, N=50000, E=800000, C=128
#define TT 2
#define MAXN 50000
#define MAXE 800000
#define CDIM 128

// Scratch (device globals: allocation-free rule). float4 arrays force 16B alignment.
__device__ float4 g_h[MAXN * (CDIM / 4)];    // 25.6 MB  (X @ W product)
__device__ float4 g_agg[MAXN * (CDIM / 4)];  // 25.6 MB  (conv1 aggregation output)
__device__ float  g_dinv[MAXN];              // rsqrt(1 + deg)
__device__ int    g_eidx[TT * 2 * MAXE];     // 12.8 MB  (edge indices as int32)
__device__ int    g_hist[MAXN];              // per-dst degree histogram
__device__ int    g_rowptr[MAXN + 1];        // CSR row offsets
__device__ int    g_cursor[MAXN];            // fill cursors for permute
__device__ int    g_csr_src[MAXE];           // src node per CSR slot
__device__ int    g_is64;                    // 1 if input edge dtype is int64

// ---------------------------------------------------------------------------
// Edge-index dtype detection + conversion to int32
// ---------------------------------------------------------------------------
__global__ void k_detect(const unsigned int* __restrict__ raw, int total_elems) {
    if (blockIdx.x == 0 && threadIdx.x == 0) {
        int n = total_elems < 64 ? total_elems : 64;
        int all0 = 1;
        for (int i = 0; i < n; i++)
            if (raw[2 * i + 1] != 0u) { all0 = 0; break; }
        g_is64 = all0;
    }
}

__global__ void k_convert(const unsigned int* __restrict__ raw, int* __restrict__ out,
                          int total_elems) {
    int i = blockIdx.x * blockDim.x + threadIdx.x;
    if (i >= total_elems) return;
    const int is64 = g_is64;
    out[i] = is64 ? (int)raw[2 * (size_t)i] : (int)raw[i];
}

// ---------------------------------------------------------------------------
// CSR build: zero-hist, histogram, scan(+cursor copy), dinv, permute
// ---------------------------------------------------------------------------
__global__ void k_zero(int* p, int n) {
    int i = blockIdx.x * blockDim.x + threadIdx.x;
    if (i < n) p[i] = 0;
}

__global__ void k_hist(int* __restrict__ hist, const int* __restrict__ dst, int e) {
    int i = blockIdx.x * blockDim.x + threadIdx.x;
    if (i < e) atomicAdd(&hist[dst[i]], 1);
}

// Single-block exclusive scan (shfl-based), 1024 threads, chunked.
__global__ __launch_bounds__(1024) void k_scan(
    const int* __restrict__ hist, int* __restrict__ rowptr,
    int* __restrict__ cursor, int n)
{
    __shared__ int warp_off[32];
    __shared__ int carry_s;
    const int tid  = threadIdx.x;
    const int lane = tid & 31;
    const int wid  = tid >> 5;
    if (tid == 0) carry_s = 0;
    __syncthreads();

    for (int base = 0; base < n; base += 1024) {
        const int i = base + tid;
        const int v = (i < n) ? hist[i] : 0;
        // warp-level inclusive scan
        int x = v;
#pragma unroll
        for (int off = 1; off < 32; off <<= 1) {
            int t = __shfl_up_sync(0xffffffffu, x, off);
            if (lane >= off) x += t;
        }
        if (lane == 31) warp_off[wid] = x;   // warp totals
        __syncthreads();
        if (wid == 0) {
            int wt = warp_off[lane];
            int y = wt;
#pragma unroll
            for (int off = 1; off < 32; off <<= 1) {
                int t = __shfl_up_sync(0xffffffffu, y, off);
                if (lane >= off) y += t;
            }
            warp_off[lane] = y - wt;         // exclusive warp offsets
        }
        __syncthreads();
        const int excl = (x - v) + warp_off[wid] + carry_s;
        if (i < n) { rowptr[i] = excl; cursor[i] = excl; }
        __syncthreads();
        if (tid == 1023) carry_s += warp_off[31] + x;  // add chunk total
        __syncthreads();
    }
    if (tid == 0) rowptr[n] = carry_s;
}

__global__ void k_dinv(const int* __restrict__ hist, float* __restrict__ dinv, int n) {
    int i = blockIdx.x * blockDim.x + threadIdx.x;
    if (i < n) dinv[i] = rsqrtf(1.0f + (float)hist[i]);   // +1 for self-loop
}

__global__ void k_permute(const int* __restrict__ src, const int* __restrict__ dst,
                          int* __restrict__ cursor, int* __restrict__ csr_src, int e)
{
    int i = blockIdx.x * blockDim.x + threadIdx.x;
    if (i >= e) return;
    const int d = dst[i];
    const int pos = atomicAdd(&cursor[d], 1);
    csr_src[pos] = src[i];
}

// ---------------------------------------------------------------------------
// GEMM: Y[n,128] = f(X)[n,128] @ W[128,128]
// MODE 0: f(x) = x         MODE 1: f(x) = relu(x + bias)  (fuses conv1 epilogue)
// ---------------------------------------------------------------------------
template <int MODE>
__global__ __launch_bounds__(256) void k_gemm128(
    const float* __restrict__ X, const float* __restrict__ W,
    const float* __restrict__ bias, float* __restrict__ Y, int nrows)
{
    __shared__ float  xs[16][65];       // [k][row], +1 pad
    __shared__ float4 ws[16][32];       // [k][col/4]

    const int tid = threadIdx.x;
    const int tx  = tid & 31;           // col group (cols tx*4 .. tx*4+3)
    const int ty  = tid >> 5;           // row group (rows ty*8 .. ty*8+7)
    const int rowBase = blockIdx.x * 64;

    float4 acc[8];
#pragma unroll
    for (int r = 0; r < 8; r++) acc[r] = make_float4(0.f, 0.f, 0.f, 0.f);

    const int lrow = tid >> 2;          // 0..63
    const int lkv  = tid & 3;           // 0..3
    const int wk   = tid >> 5;          // 0..7
    const int wj   = tid & 31;          // 0..31

    for (int k0 = 0; k0 < 128; k0 += 16) {
        float4 v = make_float4(0.f, 0.f, 0.f, 0.f);
        const int grow = rowBase + lrow;
        if (grow < nrows)
            v = reinterpret_cast<const float4*>(X)[(grow * 128 + k0 + lkv * 4) >> 2];
        if (MODE == 1) {
            const float4 bv = reinterpret_cast<const float4*>(bias)[(k0 + lkv * 4) >> 2];
            v.x = fmaxf(v.x + bv.x, 0.f);
            v.y = fmaxf(v.y + bv.y, 0.f);
            v.z = fmaxf(v.z + bv.z, 0.f);
            v.w = fmaxf(v.w + bv.w, 0.f);
        }
        xs[lkv * 4 + 0][lrow] = v.x;
        xs[lkv * 4 + 1][lrow] = v.y;
        xs[lkv * 4 + 2][lrow] = v.z;
        xs[lkv * 4 + 3][lrow] = v.w;
        ws[wk][wj]     = reinterpret_cast<const float4*>(W)[((k0 + wk) * 128 + wj * 4) >> 2];
        ws[wk + 8][wj] = reinterpret_cast<const float4*>(W)[((k0 + wk + 8) * 128 + wj * 4) >> 2];
        __syncthreads();

#pragma unroll
        for (int kk = 0; kk < 16; kk++) {
            const float4 w = ws[kk][tx];
#pragma unroll
            for (int r = 0; r < 8; r++) {
                const float a = xs[kk][ty * 8 + r];
                acc[r].x = fmaf(a, w.x, acc[r].x);
                acc[r].y = fmaf(a, w.y, acc[r].y);
                acc[r].z = fmaf(a, w.z, acc[r].z);
                acc[r].w = fmaf(a, w.w, acc[r].w);
            }
        }
        __syncthreads();
    }

#pragma unroll
    for (int r = 0; r < 8; r++) {
        const int grow = rowBase + ty * 8 + r;
        if (grow < nrows)
            reinterpret_cast<float4*>(Y)[(grow * 128 + tx * 4) >> 2] = acc[r];
    }
}

// ---------------------------------------------------------------------------
// CSR gather: one warp per node.
//   out[n] = sum_{s in N(n)} h[s] * dinv[s]*dinv[n]  +  h[n] * dinv[n]^2  (+ bias)
// MODE 0: no bias (feeds conv2 GEMM which fuses relu+b1)
// MODE 1: adds b2 (final conv output, written straight to d_out)
// ---------------------------------------------------------------------------
template <int MODE>
__global__ __launch_bounds__(256) void k_gather(
    const float4* __restrict__ h, float4* __restrict__ out,
    const int* __restrict__ rowptr, const int* __restrict__ csr_src,
    const float* __restrict__ dinv, const float* __restrict__ bias, int n)
{
    const int node = blockIdx.x * 8 + (threadIdx.x >> 5);
    if (node >= n) return;
    const int lane = threadIdx.x & 31;

    const float dd = __ldg(&dinv[node]);
    const int js = __ldg(&rowptr[node]);
    const int je = __ldg(&rowptr[node + 1]);

    // self-loop
    float4 v = h[node * 32 + lane];
    const float sl = dd * dd;
    float4 acc0 = make_float4(v.x * sl, v.y * sl, v.z * sl, v.w * sl);
    float4 acc1 = make_float4(0.f, 0.f, 0.f, 0.f);

    int j = js;
    for (; j + 1 < je; j += 2) {
        const int s0 = __ldg(&csr_src[j]);
        const int s1 = __ldg(&csr_src[j + 1]);
        const float w0 = dd * __ldg(&dinv[s0]);
        const float w1 = dd * __ldg(&dinv[s1]);
        const float4 v0 = h[s0 * 32 + lane];
        const float4 v1 = h[s1 * 32 + lane];
        acc0.x = fmaf(v0.x, w0, acc0.x); acc0.y = fmaf(v0.y, w0, acc0.y);
        acc0.z = fmaf(v0.z, w0, acc0.z); acc0.w = fmaf(v0.w, w0, acc0.w);
        acc1.x = fmaf(v1.x, w1, acc1.x); acc1.y = fmaf(v1.y, w1, acc1.y);
        acc1.z = fmaf(v1.z, w1, acc1.z); acc1.w = fmaf(v1.w, w1, acc1.w);
    }
    if (j < je) {
        const int s0 = __ldg(&csr_src[j]);
        const float w0 = dd * __ldg(&dinv[s0]);
        const float4 v0 = h[s0 * 32 + lane];
        acc0.x = fmaf(v0.x, w0, acc0.x); acc0.y = fmaf(v0.y, w0, acc0.y);
        acc0.z = fmaf(v0.z, w0, acc0.z); acc0.w = fmaf(v0.w, w0, acc0.w);
    }
    acc0.x += acc1.x; acc0.y += acc1.y; acc0.z += acc1.z; acc0.w += acc1.w;

    if (MODE == 1) {
        const float4 b = reinterpret_cast<const float4*>(bias)[lane];
        acc0.x += b.x; acc0.y += b.y; acc0.z += b.z; acc0.w += b.w;
    }
    out[node * 32 + lane] = acc0;
}

// ---------------------------------------------------------------------------
// Importance: imp[n] = dot(out1[n,:], Wc) + bc   (one warp per node)
// ---------------------------------------------------------------------------
__global__ void k_importance(const float* __restrict__ out1, const float* __restrict__ Wc,
                             const float* __restrict__ bc, float* __restrict__ imp, int n)
{
    const int node = (int)((blockIdx.x * blockDim.x + threadIdx.x) >> 5);
    if (node >= n) return;
    const int lane = threadIdx.x & 31;
    const float4 a = reinterpret_cast<const float4*>(out1)[node * 32 + lane];
    const float4 w = reinterpret_cast<const float4*>(Wc)[lane];
    float s = a.x * w.x + a.y * w.y + a.z * w.z + a.w * w.w;
#pragma unroll
    for (int off = 16; off; off >>= 1) s += __shfl_xor_sync(0xffffffffu, s, off);
    if (lane == 0) imp[node] = s + bc[0];
}

// ---------------------------------------------------------------------------
// Launch
// ---------------------------------------------------------------------------
extern "C" void kernel_launch(void* const* d_in, const int* in_sizes, int n_in,
                              void* d_out, int out_size)
{
    const float*        x_seq = (const float*)d_in[0];        // [T, N, 128]
    const unsigned int* eraw  = (const unsigned int*)d_in[1]; // [T, 2, E] int32 or int64
    const float*        W1    = (const float*)d_in[2];
    const float*        b1    = (const float*)d_in[3];
    const float*        W2    = (const float*)d_in[4];
    const float*        b2    = (const float*)d_in[5];
    const float*        Wc    = (const float*)d_in[6];
    const float*        bc    = (const float*)d_in[7];

    const int N = in_sizes[0] / (TT * CDIM);
    const int E = in_sizes[1] / (TT * 2);
    const int totalE = TT * 2 * E;

    float* out  = (float*)d_out;
    float* imp  = out;          // [N]
    float* outs = out + N;      // out_t at outs + t*N*128

    float4* dh;  float4* dagg;  float* ddinv;  int* deidx;
    int* dhist;  int* drowptr;  int* dcursor;  int* dcsr;
    cudaGetSymbolAddress((void**)&dh,      g_h);
    cudaGetSymbolAddress((void**)&dagg,    g_agg);
    cudaGetSymbolAddress((void**)&ddinv,   g_dinv);
    cudaGetSymbolAddress((void**)&deidx,   g_eidx);
    cudaGetSymbolAddress((void**)&dhist,   g_hist);
    cudaGetSymbolAddress((void**)&drowptr, g_rowptr);
    cudaGetSymbolAddress((void**)&dcursor, g_cursor);
    cudaGetSymbolAddress((void**)&dcsr,    g_csr_src);

    const int TPB = 256;
    const int gN    = (N + TPB - 1) / TPB;
    const int gE    = (E + TPB - 1) / TPB;
    const int gGemm = (N + 63) / 64;
    const int gGath = (N + 7) / 8;                 // 8 warps (nodes) per block
    const int gConv = (totalE + TPB - 1) / TPB;

    // Detect int32 vs int64 edge dtype, then materialize int32 indices.
    k_detect<<<1, 32>>>(eraw, totalE);
    k_convert<<<gConv, TPB>>>(eraw, deidx, totalE);

    for (int t = 0; t < TT; t++) {
        const int* src = deidx + (size_t)t * 2 * E;
        const int* dst = src + E;
        const float* x_t = x_seq + (size_t)t * N * CDIM;
        float* out_t = outs + (size_t)t * N * CDIM;

        // CSR build (dst-sorted) + dinv
        k_zero<<<gN, TPB>>>(dhist, N);
        k_hist<<<gE, TPB>>>(dhist, dst, E);
        k_scan<<<1, 1024>>>(dhist, drowptr, dcursor, N);
        k_dinv<<<gN, TPB>>>(dhist, ddinv, N);
        k_permute<<<gE, TPB>>>(src, dst, dcursor, dcsr, E);

        // conv1: h = x_t @ W1 ; agg = gather(h)
        k_gemm128<0><<<gGemm, TPB>>>(x_t, W1, b1, (float*)dh, N);
        k_gather<0><<<gGath, TPB>>>(dh, dagg, drowptr, dcsr, ddinv, b1, N);

        // conv2: h = relu(agg + b1) @ W2 ; out_t = gather(h) + b2
        k_gemm128<1><<<gGemm, TPB>>>((const float*)dagg, W2, b1, (float*)dh, N);
        k_gather<1><<<gGath, TPB>>>(dh, (float4*)out_t, drowptr, dcsr, ddinv, b2, N);
    }

    // importance from last timestep's output
    k_importance<<<(N * 32 + TPB - 1) / TPB, TPB>>>(outs + (size_t)(TT - 1) * N * CDIM,
                                                    Wc, bc, imp, N);
}

// round 6
// speedup vs baseline: 2.0109x; 2.0109x over previous
#include <cuda_runtime.h>
#include <cuda_bf16.h>
#include <cstdint>

// Problem constants (from reference): T=2, N=50000, E=800000, C=128
#define TT 2
#define MAXN 50000
#define MAXE 800000
#define CDIM 128

// Scratch (device globals: allocation-free rule).
__device__ float4 g_h[MAXN * (CDIM / 4)];    // 25.6 MB  (X @ W product)
__device__ float4 g_agg[MAXN * (CDIM / 4)];  // 25.6 MB  (conv1 aggregation output)
__device__ float  g_dinv[MAXN];              // rsqrt(1 + deg)
__device__ int    g_eidx[TT * 2 * MAXE];     // 12.8 MB  (edge indices as int32)
__device__ int    g_hist[MAXN];              // per-dst degree histogram
__device__ int    g_rowptr[MAXN + 1];        // CSR row offsets
__device__ int    g_cursor[MAXN];            // fill cursors for permute
__device__ int    g_csr_src[MAXE];           // src node per CSR slot
__device__ int    g_bsum[64];                // per-1024-chunk sums for scan
__device__ int    g_is64;                    // 1 if input edge dtype is int64

// ---------------------------------------------------------------------------
// Edge-index dtype detection + conversion to int32
// ---------------------------------------------------------------------------
__global__ void k_detect(const unsigned int* __restrict__ raw, int total_elems) {
    if (blockIdx.x == 0 && threadIdx.x == 0) {
        int n = total_elems < 64 ? total_elems : 64;
        int all0 = 1;
        for (int i = 0; i < n; i++)
            if (raw[2 * i + 1] != 0u) { all0 = 0; break; }
        g_is64 = all0;
    }
}

__global__ void k_convert(const unsigned int* __restrict__ raw, int* __restrict__ out,
                          int total_elems) {
    int i = blockIdx.x * blockDim.x + threadIdx.x;
    if (i >= total_elems) return;
    const int is64 = g_is64;
    out[i] = is64 ? (int)raw[2 * (size_t)i] : (int)raw[i];
}

// ---------------------------------------------------------------------------
// CSR build: zero, histogram, 3-stage parallel scan, dinv, permute
// ---------------------------------------------------------------------------
__global__ void k_zero(int* p, int n) {
    int i = blockIdx.x * blockDim.x + threadIdx.x;
    if (i < n) p[i] = 0;
}

__global__ void k_hist(int* __restrict__ hist, const int* __restrict__ dst, int e) {
    int i = blockIdx.x * blockDim.x + threadIdx.x;
    if (i < e) atomicAdd(&hist[dst[i]], 1);
}

// Stage 1: per-block (1024-element chunk) sums.
__global__ __launch_bounds__(256) void k_bsum(const int* __restrict__ hist,
                                              int* __restrict__ bsum, int n) {
    __shared__ int ws[8];
    const int tid = threadIdx.x;
    const int base = blockIdx.x * 1024;
    int s = 0;
#pragma unroll
    for (int k = 0; k < 4; k++) {
        int i = base + k * 256 + tid;
        if (i < n) s += hist[i];
    }
#pragma unroll
    for (int o = 16; o; o >>= 1) s += __shfl_xor_sync(0xffffffffu, s, o);
    if ((tid & 31) == 0) ws[tid >> 5] = s;
    __syncthreads();
    if (tid < 32) {
        int v = (tid < 8) ? ws[tid] : 0;
#pragma unroll
        for (int o = 4; o; o >>= 1) v += __shfl_xor_sync(0xffffffffu, v, o);
        if (tid == 0) bsum[blockIdx.x] = v;
    }
}

// Stage 2: exclusive scan of <=64 block sums; also writes rowptr[n] = total.
__global__ void k_scanb(int* __restrict__ bsum, int* __restrict__ rowptr, int nb, int n) {
    __shared__ int w0tot;
    const int tid = threadIdx.x;  // 64 threads
    const int lane = tid & 31;
    int v = (tid < nb) ? bsum[tid] : 0;
    int x = v;
#pragma unroll
    for (int o = 1; o < 32; o <<= 1) {
        int u = __shfl_up_sync(0xffffffffu, x, o);
        if (lane >= o) x += u;
    }
    if (tid == 31) w0tot = x;
    __syncthreads();
    int excl = x - v + (tid >= 32 ? w0tot : 0);
    if (tid < nb) bsum[tid] = excl;
    if (tid == nb - 1) rowptr[n] = excl + v;
}

// Stage 3: per-block rescan + global offset -> rowptr, cursor.
__global__ __launch_bounds__(256) void k_rowptr(const int* __restrict__ hist,
                                                const int* __restrict__ boff,
                                                int* __restrict__ rowptr,
                                                int* __restrict__ cursor, int n) {
    __shared__ int wsum[8];
    const int tid = threadIdx.x, lane = tid & 31, wid = tid >> 5;
    const int i0 = blockIdx.x * 1024 + tid * 4;
    int v0 = (i0     < n) ? hist[i0]     : 0;
    int v1 = (i0 + 1 < n) ? hist[i0 + 1] : 0;
    int v2 = (i0 + 2 < n) ? hist[i0 + 2] : 0;
    int v3 = (i0 + 3 < n) ? hist[i0 + 3] : 0;
    const int t = v0 + v1 + v2 + v3;
    int x = t;
#pragma unroll
    for (int o = 1; o < 32; o <<= 1) {
        int u = __shfl_up_sync(0xffffffffu, x, o);
        if (lane >= o) x += u;
    }
    if (lane == 31) wsum[wid] = x;
    __syncthreads();
    if (wid == 0) {
        int wv = (lane < 8) ? wsum[lane] : 0;
        int y = wv;
#pragma unroll
        for (int o = 1; o < 8; o <<= 1) {
            int u = __shfl_up_sync(0xffffffffu, y, o);
            if (lane >= o) y += u;
        }
        if (lane < 8) wsum[lane] = y - wv;
    }
    __syncthreads();
    int e0 = (x - t) + wsum[wid] + boff[blockIdx.x];
    int e1 = e0 + v0, e2 = e1 + v1, e3 = e2 + v2;
    if (i0     < n) { rowptr[i0]     = e0; cursor[i0]     = e0; }
    if (i0 + 1 < n) { rowptr[i0 + 1] = e1; cursor[i0 + 1] = e1; }
    if (i0 + 2 < n) { rowptr[i0 + 2] = e2; cursor[i0 + 2] = e2; }
    if (i0 + 3 < n) { rowptr[i0 + 3] = e3; cursor[i0 + 3] = e3; }
}

__global__ void k_dinv(const int* __restrict__ hist, float* __restrict__ dinv, int n) {
    int i = blockIdx.x * blockDim.x + threadIdx.x;
    if (i < n) dinv[i] = rsqrtf(1.0f + (float)hist[i]);   // +1 for self-loop
}

__global__ void k_permute(const int* __restrict__ src, const int* __restrict__ dst,
                          int* __restrict__ cursor, int* __restrict__ csr_src, int e)
{
    int i = blockIdx.x * blockDim.x + threadIdx.x;
    if (i >= e) return;
    const int d = dst[i];
    const int pos = atomicAdd(&cursor[d], 1);
    csr_src[pos] = src[i];
}

// ---------------------------------------------------------------------------
// Tensor-core GEMM: Y[n,128] = f(X)[n,128] @ W[128,128]
// bf16 2-way split (3 MMA terms): X=Xh+Xl, W=Wh+Wl; Y = XhWh + XhWl + XlWh.
// mode 0: f(x) = x    mode 1: f(x) = relu(x + bias)
// Block: 256 threads (8 warps), M-tile 128, full K=128 resident.
// smem: Ah, Al, Wh, Wl each [128][136] bf16  -> 139264 B dynamic.
// ---------------------------------------------------------------------------
#define SPAD 136
#define GEMM_SMEM (4 * 128 * SPAD * 2)

__device__ __forceinline__ void store_split(__nv_bfloat16* H, __nv_bfloat16* L,
                                            int off, float4 v) {
    __nv_bfloat16 h0 = __float2bfloat16(v.x);
    __nv_bfloat16 h1 = __float2bfloat16(v.y);
    __nv_bfloat16 h2 = __float2bfloat16(v.z);
    __nv_bfloat16 h3 = __float2bfloat16(v.w);
    __nv_bfloat16 l0 = __float2bfloat16(v.x - __bfloat162float(h0));
    __nv_bfloat16 l1 = __float2bfloat16(v.y - __bfloat162float(h1));
    __nv_bfloat16 l2 = __float2bfloat16(v.z - __bfloat162float(h2));
    __nv_bfloat16 l3 = __float2bfloat16(v.w - __bfloat162float(h3));
    uint2 ph, pl;
    ph.x = (uint32_t)__bfloat16_as_ushort(h0) | ((uint32_t)__bfloat16_as_ushort(h1) << 16);
    ph.y = (uint32_t)__bfloat16_as_ushort(h2) | ((uint32_t)__bfloat16_as_ushort(h3) << 16);
    pl.x = (uint32_t)__bfloat16_as_ushort(l0) | ((uint32_t)__bfloat16_as_ushort(l1) << 16);
    pl.y = (uint32_t)__bfloat16_as_ushort(l2) | ((uint32_t)__bfloat16_as_ushort(l3) << 16);
    *reinterpret_cast<uint2*>(H + off) = ph;
    *reinterpret_cast<uint2*>(L + off) = pl;
}

#define LDSM_X4(r0, r1, r2, r3, addr)                                          \
    asm volatile("ldmatrix.sync.aligned.m8n8.x4.shared.b16 {%0,%1,%2,%3}, [%4];" \
                 : "=r"(r0), "=r"(r1), "=r"(r2), "=r"(r3) : "r"(addr))

#define LDSM_X4T(r0, r1, r2, r3, addr)                                         \
    asm volatile("ldmatrix.sync.aligned.m8n8.x4.trans.shared.b16 {%0,%1,%2,%3}, [%4];" \
                 : "=r"(r0), "=r"(r1), "=r"(r2), "=r"(r3) : "r"(addr))

#define MMA16816(C, a0, a1, a2, a3, b0, b1)                                    \
    asm volatile("mma.sync.aligned.m16n8k16.row.col.f32.bf16.bf16.f32 "        \
                 "{%0,%1,%2,%3}, {%4,%5,%6,%7}, {%8,%9}, {%0,%1,%2,%3};"       \
                 : "+f"(C[0]), "+f"(C[1]), "+f"(C[2]), "+f"(C[3])              \
                 : "r"(a0), "r"(a1), "r"(a2), "r"(a3), "r"(b0), "r"(b1))

__global__ __launch_bounds__(256) void k_gemm_mma(
    const float* __restrict__ X, const float* __restrict__ W,
    const float* __restrict__ bias, float* __restrict__ Y, int nrows, int mode)
{
    extern __shared__ __nv_bfloat16 sm[];
    __nv_bfloat16* Ah = sm;
    __nv_bfloat16* Al = Ah + 128 * SPAD;
    __nv_bfloat16* Wh = Al + 128 * SPAD;
    __nv_bfloat16* Wl = Wh + 128 * SPAD;

    const int tid = threadIdx.x;
    const int lane = tid & 31, wid = tid >> 5;
    const int rowBase = blockIdx.x * 128;

    // Load + split W (128x128 f32, 4096 float4s)
#pragma unroll
    for (int it = 0; it < 16; it++) {
        const int idx = it * 256 + tid;
        const int row = idx >> 5;
        const int c4  = idx & 31;
        const float4 v = reinterpret_cast<const float4*>(W)[idx];
        store_split(Wh, Wl, row * SPAD + c4 * 4, v);
    }
    // Load + split X tile (with optional relu+bias)
#pragma unroll
    for (int it = 0; it < 16; it++) {
        const int idx = it * 256 + tid;
        const int row = idx >> 5;
        const int c4  = idx & 31;
        const int grow = rowBase + row;
        float4 v = make_float4(0.f, 0.f, 0.f, 0.f);
        if (grow < nrows) v = reinterpret_cast<const float4*>(X)[grow * 32 + c4];
        if (mode == 1) {
            const float4 b = reinterpret_cast<const float4*>(bias)[c4];
            v.x = fmaxf(v.x + b.x, 0.f);
            v.y = fmaxf(v.y + b.y, 0.f);
            v.z = fmaxf(v.z + b.z, 0.f);
            v.w = fmaxf(v.w + b.w, 0.f);
        }
        store_split(Ah, Al, row * SPAD + c4 * 4, v);
    }
    __syncthreads();

    const uint32_t sb = (uint32_t)__cvta_generic_to_shared(sm);
    const uint32_t HALF = 128 * SPAD * 2;          // bytes between Ah/Al and Wh/Wl
    const int sub = lane >> 3, li = lane & 7;

    // A-frag address pieces (per-lane)
    const int arow = wid * 16 + ((sub & 1) << 3) + li;
    const int acol0 = (sub >> 1) << 3;
    // B-frag address pieces
    const int bkrow0 = ((sub & 1) << 3) + li;
    const int bncol0 = (sub >> 1) << 3;

    float acc[16][4];
#pragma unroll
    for (int t = 0; t < 16; t++)
#pragma unroll
        for (int c = 0; c < 4; c++) acc[t][c] = 0.f;

    for (int k0 = 0; k0 < 128; k0 += 16) {
        uint32_t aaddr = sb + (uint32_t)((arow * SPAD + k0 + acol0) * 2);
        uint32_t ah0, ah1, ah2, ah3, al0, al1, al2, al3;
        LDSM_X4(ah0, ah1, ah2, ah3, aaddr);
        LDSM_X4(al0, al1, al2, al3, aaddr + HALF);

#pragma unroll
        for (int np = 0; np < 8; np++) {
            const int n0 = np * 16;
            uint32_t baddr = sb + 2u * HALF +
                (uint32_t)(((k0 + bkrow0) * SPAD + n0 + bncol0) * 2);
            uint32_t bh0, bh1, bh2, bh3, bl0, bl1, bl2, bl3;
            LDSM_X4T(bh0, bh1, bh2, bh3, baddr);
            LDSM_X4T(bl0, bl1, bl2, bl3, baddr + HALF);
            const int t0 = np * 2, t1 = t0 + 1;
            MMA16816(acc[t0], ah0, ah1, ah2, ah3, bh0, bh1);
            MMA16816(acc[t0], al0, al1, al2, al3, bh0, bh1);
            MMA16816(acc[t0], ah0, ah1, ah2, ah3, bl0, bl1);
            MMA16816(acc[t1], ah0, ah1, ah2, ah3, bh2, bh3);
            MMA16816(acc[t1], al0, al1, al2, al3, bh2, bh3);
            MMA16816(acc[t1], ah0, ah1, ah2, ah3, bl2, bl3);
        }
    }

    // Epilogue: m16n8 frag -> Y. Lane l: rows l/4, l/4+8; cols (l%4)*2, +1.
    const int r0 = rowBase + wid * 16 + (lane >> 2);
    const int c0 = (lane & 3) * 2;
#pragma unroll
    for (int nt = 0; nt < 16; nt++) {
        const int col = nt * 8 + c0;
        if (r0 < nrows) {
            float2 v = make_float2(acc[nt][0], acc[nt][1]);
            *reinterpret_cast<float2*>(&Y[r0 * 128 + col]) = v;
        }
        if (r0 + 8 < nrows) {
            float2 v = make_float2(acc[nt][2], acc[nt][3]);
            *reinterpret_cast<float2*>(&Y[(r0 + 8) * 128 + col]) = v;
        }
    }
}

// ---------------------------------------------------------------------------
// CSR gather: one warp per node, unrolled x4 for MLP.
//   out[n] = sum_{s in N(n)} h[s]*dinv[s]*dinv[n] + h[n]*dinv[n]^2 (+ bias)
// MODE 0: no bias   MODE 1: + b2 (written straight to d_out)
// ---------------------------------------------------------------------------
template <int MODE>
__global__ __launch_bounds__(256) void k_gather(
    const float4* __restrict__ h, float4* __restrict__ out,
    const int* __restrict__ rowptr, const int* __restrict__ csr_src,
    const float* __restrict__ dinv, const float* __restrict__ bias, int n)
{
    const int node = blockIdx.x * 8 + (threadIdx.x >> 5);
    if (node >= n) return;
    const int lane = threadIdx.x & 31;

    const float dd = __ldg(&dinv[node]);
    const int js = __ldg(&rowptr[node]);
    const int je = __ldg(&rowptr[node + 1]);

    float4 v = h[node * 32 + lane];
    const float sl = dd * dd;
    float4 a0 = make_float4(v.x * sl, v.y * sl, v.z * sl, v.w * sl);
    float4 a1 = make_float4(0.f, 0.f, 0.f, 0.f);
    float4 a2 = make_float4(0.f, 0.f, 0.f, 0.f);
    float4 a3 = make_float4(0.f, 0.f, 0.f, 0.f);

    int j = js;
    for (; j + 3 < je; j += 4) {
        const int s0 = __ldg(&csr_src[j]);
        const int s1 = __ldg(&csr_src[j + 1]);
        const int s2 = __ldg(&csr_src[j + 2]);
        const int s3 = __ldg(&csr_src[j + 3]);
        const float w0 = dd * __ldg(&dinv[s0]);
        const float w1 = dd * __ldg(&dinv[s1]);
        const float w2 = dd * __ldg(&dinv[s2]);
        const float w3 = dd * __ldg(&dinv[s3]);
        const float4 v0 = h[s0 * 32 + lane];
        const float4 v1 = h[s1 * 32 + lane];
        const float4 v2 = h[s2 * 32 + lane];
        const float4 v3 = h[s3 * 32 + lane];
        a0.x = fmaf(v0.x, w0, a0.x); a0.y = fmaf(v0.y, w0, a0.y);
        a0.z = fmaf(v0.z, w0, a0.z); a0.w = fmaf(v0.w, w0, a0.w);
        a1.x = fmaf(v1.x, w1, a1.x); a1.y = fmaf(v1.y, w1, a1.y);
        a1.z = fmaf(v1.z, w1, a1.z); a1.w = fmaf(v1.w, w1, a1.w);
        a2.x = fmaf(v2.x, w2, a2.x); a2.y = fmaf(v2.y, w2, a2.y);
        a2.z = fmaf(v2.z, w2, a2.z); a2.w = fmaf(v2.w, w2, a2.w);
        a3.x = fmaf(v3.x, w3, a3.x); a3.y = fmaf(v3.y, w3, a3.y);
        a3.z = fmaf(v3.z, w3, a3.z); a3.w = fmaf(v3.w, w3, a3.w);
    }
    for (; j < je; j++) {
        const int s0 = __ldg(&csr_src[j]);
        const float w0 = dd * __ldg(&dinv[s0]);
        const float4 v0 = h[s0 * 32 + lane];
        a0.x = fmaf(v0.x, w0, a0.x); a0.y = fmaf(v0.y, w0, a0.y);
        a0.z = fmaf(v0.z, w0, a0.z); a0.w = fmaf(v0.w, w0, a0.w);
    }
    a0.x += a1.x + a2.x + a3.x;
    a0.y += a1.y + a2.y + a3.y;
    a0.z += a1.z + a2.z + a3.z;
    a0.w += a1.w + a2.w + a3.w;

    if (MODE == 1) {
        const float4 b = reinterpret_cast<const float4*>(bias)[lane];
        a0.x += b.x; a0.y += b.y; a0.z += b.z; a0.w += b.w;
    }
    out[node * 32 + lane] = a0;
}

// ---------------------------------------------------------------------------
// Importance: imp[n] = dot(out1[n,:], Wc) + bc   (one warp per node)
// ---------------------------------------------------------------------------
__global__ void k_importance(const float* __restrict__ out1, const float* __restrict__ Wc,
                             const float* __restrict__ bc, float* __restrict__ imp, int n)
{
    const int node = (int)((blockIdx.x * blockDim.x + threadIdx.x) >> 5);
    if (node >= n) return;
    const int lane = threadIdx.x & 31;
    const float4 a = reinterpret_cast<const float4*>(out1)[node * 32 + lane];
    const float4 w = reinterpret_cast<const float4*>(Wc)[lane];
    float s = a.x * w.x + a.y * w.y + a.z * w.z + a.w * w.w;
#pragma unroll
    for (int off = 16; off; off >>= 1) s += __shfl_xor_sync(0xffffffffu, s, off);
    if (lane == 0) imp[node] = s + bc[0];
}

// ---------------------------------------------------------------------------
// Launch
// ---------------------------------------------------------------------------
extern "C" void kernel_launch(void* const* d_in, const int* in_sizes, int n_in,
                              void* d_out, int out_size)
{
    const float*        x_seq = (const float*)d_in[0];        // [T, N, 128]
    const unsigned int* eraw  = (const unsigned int*)d_in[1]; // [T, 2, E] int32 or int64
    const float*        W1    = (const float*)d_in[2];
    const float*        b1    = (const float*)d_in[3];
    const float*        W2    = (const float*)d_in[4];
    const float*        b2    = (const float*)d_in[5];
    const float*        Wc    = (const float*)d_in[6];
    const float*        bc    = (const float*)d_in[7];

    const int N = in_sizes[0] / (TT * CDIM);
    const int E = in_sizes[1] / (TT * 2);
    const int totalE = TT * 2 * E;

    float* out  = (float*)d_out;
    float* imp  = out;          // [N]
    float* outs = out + N;      // out_t at outs + t*N*128

    float4* dh;  float4* dagg;  float* ddinv;  int* deidx;
    int* dhist;  int* drowptr;  int* dcursor;  int* dcsr;  int* dbsum;
    cudaGetSymbolAddress((void**)&dh,      g_h);
    cudaGetSymbolAddress((void**)&dagg,    g_agg);
    cudaGetSymbolAddress((void**)&ddinv,   g_dinv);
    cudaGetSymbolAddress((void**)&deidx,   g_eidx);
    cudaGetSymbolAddress((void**)&dhist,   g_hist);
    cudaGetSymbolAddress((void**)&drowptr, g_rowptr);
    cudaGetSymbolAddress((void**)&dcursor, g_cursor);
    cudaGetSymbolAddress((void**)&dcsr,    g_csr_src);
    cudaGetSymbolAddress((void**)&dbsum,   g_bsum);

    cudaFuncSetAttribute(k_gemm_mma, cudaFuncAttributeMaxDynamicSharedMemorySize,
                         GEMM_SMEM);

    const int TPB = 256;
    const int gN    = (N + TPB - 1) / TPB;
    const int gE    = (E + TPB - 1) / TPB;
    const int gGemm = (N + 127) / 128;
    const int gGath = (N + 7) / 8;                 // 8 warps (nodes) per block
    const int gConv = (totalE + TPB - 1) / TPB;
    const int nb    = (N + 1023) / 1024;           // scan chunks (<= 64)

    // Detect int32 vs int64 edge dtype, then materialize int32 indices.
    k_detect<<<1, 32>>>(eraw, totalE);
    k_convert<<<gConv, TPB>>>(eraw, deidx, totalE);

    for (int t = 0; t < TT; t++) {
        const int* src = deidx + (size_t)t * 2 * E;
        const int* dst = src + E;
        const float* x_t = x_seq + (size_t)t * N * CDIM;
        float* out_t = outs + (size_t)t * N * CDIM;

        // CSR build (dst-sorted) + dinv
        k_zero<<<gN, TPB>>>(dhist, N);
        k_hist<<<gE, TPB>>>(dhist, dst, E);
        k_bsum<<<nb, TPB>>>(dhist, dbsum, N);
        k_scanb<<<1, 64>>>(dbsum, drowptr, nb, N);
        k_rowptr<<<nb, TPB>>>(dhist, dbsum, drowptr, dcursor, N);
        k_dinv<<<gN, TPB>>>(dhist, ddinv, N);
        k_permute<<<gE, TPB>>>(src, dst, dcursor, dcsr, E);

        // conv1: h = x_t @ W1 ; agg = gather(h)
        k_gemm_mma<<<gGemm, TPB, GEMM_SMEM>>>(x_t, W1, b1, (float*)dh, N, 0);
        k_gather<0><<<gGath, TPB>>>(dh, dagg, drowptr, dcsr, ddinv, b1, N);

        // conv2: h = relu(agg + b1) @ W2 ; out_t = gather(h) + b2
        k_gemm_mma<<<gGemm, TPB, GEMM_SMEM>>>((const float*)dagg, W2, b1, (float*)dh, N, 1);
        k_gather<1><<<gGath, TPB>>>(dh, (float4*)out_t, drowptr, dcsr, ddinv, b2, N);
    }

    // importance from last timestep's output
    k_importance<<<(N * 32 + TPB - 1) / TPB, TPB>>>(outs + (size_t)(TT - 1) * N * CDIM,
                                                    Wc, bc, imp, N);
}

// round 7
// speedup vs baseline: 2.2274x; 1.1077x over previous
#include <cuda_runtime.h>
#include <cuda_bf16.h>
#include <cuda_fp16.h>
#include <cstdint>

// Problem constants (from reference): T=2, N=50000, E=800000, C=128
#define TT 2
#define MAXN 50000
#define MAXE 800000
#define CDIM 128

// Scratch (device globals: allocation-free rule).
__device__ uint2  g_h[MAXN * 32];             // 12.8 MB  (GEMM product, fp16 rows)
__device__ float4 g_agg[MAXN * (CDIM / 4)];   // 25.6 MB  (conv1 aggregation, fp32)
__device__ float  g_dinv[TT * MAXN];          // rsqrt(1 + deg), both timesteps
__device__ int    g_eidx[TT * 2 * MAXE];      // 12.8 MB  (edge indices as int32)
__device__ int    g_hist[TT * MAXN];          // per-dst degree histogram
__device__ int    g_rowptr[TT * MAXN + 1];    // CSR row offsets (concatenated)
__device__ int    g_cursor[TT * MAXN];        // fill cursors for permute
__device__ int    g_csr_src[TT * MAXE];       // src node per CSR slot
__device__ int    g_bsum[128];                // per-1024-chunk sums for scan
__device__ int    g_is64;                     // 1 if input edge dtype is int64

// ---------------------------------------------------------------------------
// Edge-index dtype detection + conversion to int32
// ---------------------------------------------------------------------------
__global__ void k_detect(const unsigned int* __restrict__ raw, int total_elems) {
    if (blockIdx.x == 0 && threadIdx.x == 0) {
        int n = total_elems < 64 ? total_elems : 64;
        int all0 = 1;
        for (int i = 0; i < n; i++)
            if (raw[2 * i + 1] != 0u) { all0 = 0; break; }
        g_is64 = all0;
    }
}

__global__ void k_convert(const unsigned int* __restrict__ raw, int* __restrict__ out,
                          int total_elems) {
    int i = blockIdx.x * blockDim.x + threadIdx.x;
    if (i >= total_elems) return;
    const int is64 = g_is64;
    out[i] = is64 ? (int)raw[2 * (size_t)i] : (int)raw[i];
}

// ---------------------------------------------------------------------------
// Batched CSR build (both timesteps): zero, hist, 3-stage scan(+dinv), permute
// ---------------------------------------------------------------------------
__global__ void k_zero(int* p, int n) {
    int i = blockIdx.x * blockDim.x + threadIdx.x;
    if (i < n) p[i] = 0;
}

// Histogram over both timesteps' dst arrays into hist[t*N + d].
__global__ void k_hist2(int* __restrict__ hist, const int* __restrict__ eidx,
                        int E, int N) {
    int i = blockIdx.x * blockDim.x + threadIdx.x;
    if (i >= 2 * E) return;
    const int t = (i >= E) ? 1 : 0;
    const int eid = i - t * E;
    const int d = eidx[t * 2 * E + E + eid];
    atomicAdd(&hist[t * N + d], 1);
}

// Stage 1: per-1024-chunk sums.
__global__ __launch_bounds__(256) void k_bsum(const int* __restrict__ hist,
                                              int* __restrict__ bsum, int n) {
    __shared__ int ws[8];
    const int tid = threadIdx.x;
    const int base = blockIdx.x * 1024;
    int s = 0;
#pragma unroll
    for (int k = 0; k < 4; k++) {
        int i = base + k * 256 + tid;
        if (i < n) s += hist[i];
    }
#pragma unroll
    for (int o = 16; o; o >>= 1) s += __shfl_xor_sync(0xffffffffu, s, o);
    if ((tid & 31) == 0) ws[tid >> 5] = s;
    __syncthreads();
    if (tid < 32) {
        int v = (tid < 8) ? ws[tid] : 0;
#pragma unroll
        for (int o = 4; o; o >>= 1) v += __shfl_xor_sync(0xffffffffu, v, o);
        if (tid == 0) bsum[blockIdx.x] = v;
    }
}

// Stage 2: exclusive scan of <=128 chunk sums; writes rowptr[n2] = total.
__global__ __launch_bounds__(128) void k_scanb(int* __restrict__ bsum,
                                               int* __restrict__ rowptr,
                                               int nb, int n2) {
    __shared__ int ws[4];
    const int tid = threadIdx.x, lane = tid & 31, wid = tid >> 5;
    int v = (tid < nb) ? bsum[tid] : 0;
    int x = v;
#pragma unroll
    for (int o = 1; o < 32; o <<= 1) {
        int u = __shfl_up_sync(0xffffffffu, x, o);
        if (lane >= o) x += u;
    }
    if (lane == 31) ws[wid] = x;
    __syncthreads();
    if (wid == 0) {
        int wv = (lane < 4) ? ws[lane] : 0;
        int y = wv;
#pragma unroll
        for (int o = 1; o < 4; o <<= 1) {
            int u = __shfl_up_sync(0xffffffffu, y, o);
            if (lane >= o) y += u;
        }
        if (lane < 4) ws[lane] = y - wv;
    }
    __syncthreads();
    const int excl = x - v + ws[wid];
    if (tid < nb) bsum[tid] = excl;
    if (tid == nb - 1) rowptr[n2] = excl + v;
}

// Stage 3: per-chunk rescan + offset -> rowptr, cursor; fused dinv.
__global__ __launch_bounds__(256) void k_rowptr(const int* __restrict__ hist,
                                                const int* __restrict__ boff,
                                                int* __restrict__ rowptr,
                                                int* __restrict__ cursor,
                                                float* __restrict__ dinv, int n) {
    __shared__ int wsum[8];
    const int tid = threadIdx.x, lane = tid & 31, wid = tid >> 5;
    const int i0 = blockIdx.x * 1024 + tid * 4;
    int v0 = (i0     < n) ? hist[i0]     : 0;
    int v1 = (i0 + 1 < n) ? hist[i0 + 1] : 0;
    int v2 = (i0 + 2 < n) ? hist[i0 + 2] : 0;
    int v3 = (i0 + 3 < n) ? hist[i0 + 3] : 0;
    const int t = v0 + v1 + v2 + v3;
    int x = t;
#pragma unroll
    for (int o = 1; o < 32; o <<= 1) {
        int u = __shfl_up_sync(0xffffffffu, x, o);
        if (lane >= o) x += u;
    }
    if (lane == 31) wsum[wid] = x;
    __syncthreads();
    if (wid == 0) {
        int wv = (lane < 8) ? wsum[lane] : 0;
        int y = wv;
#pragma unroll
        for (int o = 1; o < 8; o <<= 1) {
            int u = __shfl_up_sync(0xffffffffu, y, o);
            if (lane >= o) y += u;
        }
        if (lane < 8) wsum[lane] = y - wv;
    }
    __syncthreads();
    int e0 = (x - t) + wsum[wid] + boff[blockIdx.x];
    int e1 = e0 + v0, e2 = e1 + v1, e3 = e2 + v2;
    if (i0     < n) { rowptr[i0]     = e0; cursor[i0]     = e0; dinv[i0]     = rsqrtf(1.0f + (float)v0); }
    if (i0 + 1 < n) { rowptr[i0 + 1] = e1; cursor[i0 + 1] = e1; dinv[i0 + 1] = rsqrtf(1.0f + (float)v1); }
    if (i0 + 2 < n) { rowptr[i0 + 2] = e2; cursor[i0 + 2] = e2; dinv[i0 + 2] = rsqrtf(1.0f + (float)v2); }
    if (i0 + 3 < n) { rowptr[i0 + 3] = e3; cursor[i0 + 3] = e3; dinv[i0 + 3] = rsqrtf(1.0f + (float)v3); }
}

// Permute over both timesteps' edges into concatenated csr_src.
__global__ void k_permute2(const int* __restrict__ eidx, int* __restrict__ cursor,
                           int* __restrict__ csr_src, int E, int N) {
    int i = blockIdx.x * blockDim.x + threadIdx.x;
    if (i >= 2 * E) return;
    const int t = (i >= E) ? 1 : 0;
    const int eid = i - t * E;
    const int s = eidx[t * 2 * E + eid];
    const int d = eidx[t * 2 * E + E + eid];
    const int pos = atomicAdd(&cursor[t * N + d], 1);
    csr_src[pos] = s;
}

// ---------------------------------------------------------------------------
// Tensor-core GEMM: Yh[n,128] (fp16) = f(X)[n,128] (fp32) @ W[128,128]
// bf16 2-way split (3 MMA terms). mode 0: f(x)=x   mode 1: f(x)=relu(x+bias)
// ---------------------------------------------------------------------------
#define SPAD 136
#define GEMM_SMEM (4 * 128 * SPAD * 2)

__device__ __forceinline__ void store_split(__nv_bfloat16* H, __nv_bfloat16* L,
                                            int off, float4 v) {
    __nv_bfloat16 h0 = __float2bfloat16(v.x);
    __nv_bfloat16 h1 = __float2bfloat16(v.y);
    __nv_bfloat16 h2 = __float2bfloat16(v.z);
    __nv_bfloat16 h3 = __float2bfloat16(v.w);
    __nv_bfloat16 l0 = __float2bfloat16(v.x - __bfloat162float(h0));
    __nv_bfloat16 l1 = __float2bfloat16(v.y - __bfloat162float(h1));
    __nv_bfloat16 l2 = __float2bfloat16(v.z - __bfloat162float(h2));
    __nv_bfloat16 l3 = __float2bfloat16(v.w - __bfloat162float(h3));
    uint2 ph, pl;
    ph.x = (uint32_t)__bfloat16_as_ushort(h0) | ((uint32_t)__bfloat16_as_ushort(h1) << 16);
    ph.y = (uint32_t)__bfloat16_as_ushort(h2) | ((uint32_t)__bfloat16_as_ushort(h3) << 16);
    pl.x = (uint32_t)__bfloat16_as_ushort(l0) | ((uint32_t)__bfloat16_as_ushort(l1) << 16);
    pl.y = (uint32_t)__bfloat16_as_ushort(l2) | ((uint32_t)__bfloat16_as_ushort(l3) << 16);
    *reinterpret_cast<uint2*>(H + off) = ph;
    *reinterpret_cast<uint2*>(L + off) = pl;
}

#define LDSM_X4(r0, r1, r2, r3, addr)                                          \
    asm volatile("ldmatrix.sync.aligned.m8n8.x4.shared.b16 {%0,%1,%2,%3}, [%4];" \
                 : "=r"(r0), "=r"(r1), "=r"(r2), "=r"(r3) : "r"(addr))

#define LDSM_X4T(r0, r1, r2, r3, addr)                                         \
    asm volatile("ldmatrix.sync.aligned.m8n8.x4.trans.shared.b16 {%0,%1,%2,%3}, [%4];" \
                 : "=r"(r0), "=r"(r1), "=r"(r2), "=r"(r3) : "r"(addr))

#define MMA16816(C, a0, a1, a2, a3, b0, b1)                                    \
    asm volatile("mma.sync.aligned.m16n8k16.row.col.f32.bf16.bf16.f32 "        \
                 "{%0,%1,%2,%3}, {%4,%5,%6,%7}, {%8,%9}, {%0,%1,%2,%3};"       \
                 : "+f"(C[0]), "+f"(C[1]), "+f"(C[2]), "+f"(C[3])              \
                 : "r"(a0), "r"(a1), "r"(a2), "r"(a3), "r"(b0), "r"(b1))

__global__ __launch_bounds__(256) void k_gemm_mma(
    const float* __restrict__ X, const float* __restrict__ W,
    const float* __restrict__ bias, __half* __restrict__ Y, int nrows, int mode)
{
    extern __shared__ __nv_bfloat16 sm[];
    __nv_bfloat16* Ah = sm;
    __nv_bfloat16* Al = Ah + 128 * SPAD;
    __nv_bfloat16* Wh = Al + 128 * SPAD;
    __nv_bfloat16* Wl = Wh + 128 * SPAD;

    const int tid = threadIdx.x;
    const int lane = tid & 31, wid = tid >> 5;
    const int rowBase = blockIdx.x * 128;

#pragma unroll
    for (int it = 0; it < 16; it++) {
        const int idx = it * 256 + tid;
        const int row = idx >> 5;
        const int c4  = idx & 31;
        const float4 v = reinterpret_cast<const float4*>(W)[idx];
        store_split(Wh, Wl, row * SPAD + c4 * 4, v);
    }
#pragma unroll
    for (int it = 0; it < 16; it++) {
        const int idx = it * 256 + tid;
        const int row = idx >> 5;
        const int c4  = idx & 31;
        const int grow = rowBase + row;
        float4 v = make_float4(0.f, 0.f, 0.f, 0.f);
        if (grow < nrows) v = reinterpret_cast<const float4*>(X)[grow * 32 + c4];
        if (mode == 1) {
            const float4 b = reinterpret_cast<const float4*>(bias)[c4];
            v.x = fmaxf(v.x + b.x, 0.f);
            v.y = fmaxf(v.y + b.y, 0.f);
            v.z = fmaxf(v.z + b.z, 0.f);
            v.w = fmaxf(v.w + b.w, 0.f);
        }
        store_split(Ah, Al, row * SPAD + c4 * 4, v);
    }
    __syncthreads();

    const uint32_t sb = (uint32_t)__cvta_generic_to_shared(sm);
    const uint32_t HALF = 128 * SPAD * 2;
    const int sub = lane >> 3, li = lane & 7;
    const int arow = wid * 16 + ((sub & 1) << 3) + li;
    const int acol0 = (sub >> 1) << 3;
    const int bkrow0 = ((sub & 1) << 3) + li;
    const int bncol0 = (sub >> 1) << 3;

    float acc[16][4];
#pragma unroll
    for (int t = 0; t < 16; t++)
#pragma unroll
        for (int c = 0; c < 4; c++) acc[t][c] = 0.f;

    for (int k0 = 0; k0 < 128; k0 += 16) {
        uint32_t aaddr = sb + (uint32_t)((arow * SPAD + k0 + acol0) * 2);
        uint32_t ah0, ah1, ah2, ah3, al0, al1, al2, al3;
        LDSM_X4(ah0, ah1, ah2, ah3, aaddr);
        LDSM_X4(al0, al1, al2, al3, aaddr + HALF);

#pragma unroll
        for (int np = 0; np < 8; np++) {
            const int n0 = np * 16;
            uint32_t baddr = sb + 2u * HALF +
                (uint32_t)(((k0 + bkrow0) * SPAD + n0 + bncol0) * 2);
            uint32_t bh0, bh1, bh2, bh3, bl0, bl1, bl2, bl3;
            LDSM_X4T(bh0, bh1, bh2, bh3, baddr);
            LDSM_X4T(bl0, bl1, bl2, bl3, baddr + HALF);
            const int t0 = np * 2, t1 = t0 + 1;
            MMA16816(acc[t0], ah0, ah1, ah2, ah3, bh0, bh1);
            MMA16816(acc[t0], al0, al1, al2, al3, bh0, bh1);
            MMA16816(acc[t0], ah0, ah1, ah2, ah3, bl0, bl1);
            MMA16816(acc[t1], ah0, ah1, ah2, ah3, bh2, bh3);
            MMA16816(acc[t1], al0, al1, al2, al3, bh2, bh3);
            MMA16816(acc[t1], ah0, ah1, ah2, ah3, bl2, bl3);
        }
    }

    // Epilogue -> fp16. Lane l: rows l/4, l/4+8; cols (l%4)*2, +1.
    const int r0 = rowBase + wid * 16 + (lane >> 2);
    const int c0 = (lane & 3) * 2;
#pragma unroll
    for (int nt = 0; nt < 16; nt++) {
        const int col = nt * 8 + c0;
        if (r0 < nrows)
            *reinterpret_cast<__half2*>(&Y[r0 * 128 + col]) =
                __floats2half2_rn(acc[nt][0], acc[nt][1]);
        if (r0 + 8 < nrows)
            *reinterpret_cast<__half2*>(&Y[(r0 + 8) * 128 + col]) =
                __floats2half2_rn(acc[nt][2], acc[nt][3]);
    }
}

// ---------------------------------------------------------------------------
// CSR gather: one warp per node, fp16 input rows (uint2 = 4 halfs per lane).
//   out[n] = sum_{s in N(n)} h[s]*dinv[s]*dinv[n] + h[n]*dinv[n]^2 (+ bias)
// ---------------------------------------------------------------------------
__device__ __forceinline__ float4 h4_to_f4(uint2 u) {
    const __half2 a = *reinterpret_cast<__half2*>(&u.x);
    const __half2 b = *reinterpret_cast<__half2*>(&u.y);
    const float2 fa = __half22float2(a), fb = __half22float2(b);
    return make_float4(fa.x, fa.y, fb.x, fb.y);
}

template <int MODE>
__global__ __launch_bounds__(256) void k_gather(
    const uint2* __restrict__ h, float4* __restrict__ out,
    const int* __restrict__ rowptr, const int* __restrict__ csr_src,
    const float* __restrict__ dinv, const float* __restrict__ bias, int n)
{
    const int node = blockIdx.x * 8 + (threadIdx.x >> 5);
    if (node >= n) return;
    const int lane = threadIdx.x & 31;

    const float dd = __ldg(&dinv[node]);
    const int js = __ldg(&rowptr[node]);
    const int je = __ldg(&rowptr[node + 1]);

    const float4 v = h4_to_f4(h[node * 32 + lane]);
    const float sl = dd * dd;
    float4 a0 = make_float4(v.x * sl, v.y * sl, v.z * sl, v.w * sl);
    float4 a1 = make_float4(0.f, 0.f, 0.f, 0.f);
    float4 a2 = make_float4(0.f, 0.f, 0.f, 0.f);
    float4 a3 = make_float4(0.f, 0.f, 0.f, 0.f);

    int j = js;
    for (; j + 3 < je; j += 4) {
        const int s0 = __ldg(&csr_src[j]);
        const int s1 = __ldg(&csr_src[j + 1]);
        const int s2 = __ldg(&csr_src[j + 2]);
        const int s3 = __ldg(&csr_src[j + 3]);
        const float w0 = dd * __ldg(&dinv[s0]);
        const float w1 = dd * __ldg(&dinv[s1]);
        const float w2 = dd * __ldg(&dinv[s2]);
        const float w3 = dd * __ldg(&dinv[s3]);
        const float4 v0 = h4_to_f4(h[s0 * 32 + lane]);
        const float4 v1 = h4_to_f4(h[s1 * 32 + lane]);
        const float4 v2 = h4_to_f4(h[s2 * 32 + lane]);
        const float4 v3 = h4_to_f4(h[s3 * 32 + lane]);
        a0.x = fmaf(v0.x, w0, a0.x); a0.y = fmaf(v0.y, w0, a0.y);
        a0.z = fmaf(v0.z, w0, a0.z); a0.w = fmaf(v0.w, w0, a0.w);
        a1.x = fmaf(v1.x, w1, a1.x); a1.y = fmaf(v1.y, w1, a1.y);
        a1.z = fmaf(v1.z, w1, a1.z); a1.w = fmaf(v1.w, w1, a1.w);
        a2.x = fmaf(v2.x, w2, a2.x); a2.y = fmaf(v2.y, w2, a2.y);
        a2.z = fmaf(v2.z, w2, a2.z); a2.w = fmaf(v2.w, w2, a2.w);
        a3.x = fmaf(v3.x, w3, a3.x); a3.y = fmaf(v3.y, w3, a3.y);
        a3.z = fmaf(v3.z, w3, a3.z); a3.w = fmaf(v3.w, w3, a3.w);
    }
    for (; j < je; j++) {
        const int s0 = __ldg(&csr_src[j]);
        const float w0 = dd * __ldg(&dinv[s0]);
        const float4 v0 = h4_to_f4(h[s0 * 32 + lane]);
        a0.x = fmaf(v0.x, w0, a0.x); a0.y = fmaf(v0.y, w0, a0.y);
        a0.z = fmaf(v0.z, w0, a0.z); a0.w = fmaf(v0.w, w0, a0.w);
    }
    a0.x += a1.x + a2.x + a3.x;
    a0.y += a1.y + a2.y + a3.y;
    a0.z += a1.z + a2.z + a3.z;
    a0.w += a1.w + a2.w + a3.w;

    if (MODE == 1) {
        const float4 b = reinterpret_cast<const float4*>(bias)[lane];
        a0.x += b.x; a0.y += b.y; a0.z += b.z; a0.w += b.w;
    }
    out[node * 32 + lane] = a0;
}

// ---------------------------------------------------------------------------
// Importance: imp[n] = dot(out1[n,:], Wc) + bc   (one warp per node)
// ---------------------------------------------------------------------------
__global__ void k_importance(const float* __restrict__ out1, const float* __restrict__ Wc,
                             const float* __restrict__ bc, float* __restrict__ imp, int n)
{
    const int node = (int)((blockIdx.x * blockDim.x + threadIdx.x) >> 5);
    if (node >= n) return;
    const int lane = threadIdx.x & 31;
    const float4 a = reinterpret_cast<const float4*>(out1)[node * 32 + lane];
    const float4 w = reinterpret_cast<const float4*>(Wc)[lane];
    float s = a.x * w.x + a.y * w.y + a.z * w.z + a.w * w.w;
#pragma unroll
    for (int off = 16; off; off >>= 1) s += __shfl_xor_sync(0xffffffffu, s, off);
    if (lane == 0) imp[node] = s + bc[0];
}

// ---------------------------------------------------------------------------
// Launch
// ---------------------------------------------------------------------------
extern "C" void kernel_launch(void* const* d_in, const int* in_sizes, int n_in,
                              void* d_out, int out_size)
{
    const float*        x_seq = (const float*)d_in[0];        // [T, N, 128]
    const unsigned int* eraw  = (const unsigned int*)d_in[1]; // [T, 2, E] int32 or int64
    const float*        W1    = (const float*)d_in[2];
    const float*        b1    = (const float*)d_in[3];
    const float*        W2    = (const float*)d_in[4];
    const float*        b2    = (const float*)d_in[5];
    const float*        Wc    = (const float*)d_in[6];
    const float*        bc    = (const float*)d_in[7];

    const int N = in_sizes[0] / (TT * CDIM);
    const int E = in_sizes[1] / (TT * 2);
    const int totalE = TT * 2 * E;
    const int n2 = TT * N;

    float* out  = (float*)d_out;
    float* imp  = out;          // [N]
    float* outs = out + N;      // out_t at outs + t*N*128

    uint2* dh;  float4* dagg;  float* ddinv;  int* deidx;
    int* dhist;  int* drowptr;  int* dcursor;  int* dcsr;  int* dbsum;
    cudaGetSymbolAddress((void**)&dh,      g_h);
    cudaGetSymbolAddress((void**)&dagg,    g_agg);
    cudaGetSymbolAddress((void**)&ddinv,   g_dinv);
    cudaGetSymbolAddress((void**)&deidx,   g_eidx);
    cudaGetSymbolAddress((void**)&dhist,   g_hist);
    cudaGetSymbolAddress((void**)&drowptr, g_rowptr);
    cudaGetSymbolAddress((void**)&dcursor, g_cursor);
    cudaGetSymbolAddress((void**)&dcsr,    g_csr_src);
    cudaGetSymbolAddress((void**)&dbsum,   g_bsum);

    cudaFuncSetAttribute(k_gemm_mma, cudaFuncAttributeMaxDynamicSharedMemorySize,
                         GEMM_SMEM);

    const int TPB = 256;
    const int gGemm = (N + 127) / 128;
    const int gGath = (N + 7) / 8;                 // 8 warps (nodes) per block
    const int gConv = (totalE + TPB - 1) / TPB;
    const int g2E   = (2 * E + TPB - 1) / TPB;
    const int g2N   = (n2 + TPB - 1) / TPB;
    const int nb    = (n2 + 1023) / 1024;          // scan chunks (<= 128)

    // Detect int32 vs int64 edge dtype, then materialize int32 indices.
    k_detect<<<1, 32>>>(eraw, totalE);
    k_convert<<<gConv, TPB>>>(eraw, deidx, totalE);

    // Batched CSR build for both timesteps.
    k_zero<<<g2N, TPB>>>(dhist, n2);
    k_hist2<<<g2E, TPB>>>(dhist, deidx, E, N);
    k_bsum<<<nb, TPB>>>(dhist, dbsum, n2);
    k_scanb<<<1, 128>>>(dbsum, drowptr, nb, n2);
    k_rowptr<<<nb, TPB>>>(dhist, dbsum, drowptr, dcursor, ddinv, n2);
    k_permute2<<<g2E, TPB>>>(deidx, dcursor, dcsr, E, N);

    for (int t = 0; t < TT; t++) {
        const float* x_t = x_seq + (size_t)t * N * CDIM;
        float* out_t = outs + (size_t)t * N * CDIM;
        const int* rp = drowptr + (size_t)t * N;
        const float* dv = ddinv + (size_t)t * N;

        // conv1: h = x_t @ W1 (fp16) ; agg = gather(h) (fp32)
        k_gemm_mma<<<gGemm, TPB, GEMM_SMEM>>>(x_t, W1, b1, (__half*)dh, N, 0);
        k_gather<0><<<gGath, TPB>>>(dh, dagg, rp, dcsr, dv, b1, N);

        // conv2: h = relu(agg + b1) @ W2 (fp16) ; out_t = gather(h) + b2
        k_gemm_mma<<<gGemm, TPB, GEMM_SMEM>>>((const float*)dagg, W2, b1, (__half*)dh, N, 1);
        k_gather<1><<<gGath, TPB>>>(dh, (float4*)out_t, rp, dcsr, dv, b2, N);
    }

    // importance from last timestep's output
    k_importance<<<(N * 32 + TPB - 1) / TPB, TPB>>>(outs + (size_t)(TT - 1) * N * CDIM,
                                                    Wc, bc, imp, N);
}

// round 9
// speedup vs baseline: 2.3130x; 1.0384x over previous
#include <cuda_runtime.h>
#include <cuda_bf16.h>
#include <cuda_fp16.h>
#include <cstdint>

// Problem constants (from reference): T=2, N=50000, E=800000, C=128
#define TT 2
#define MAXN 50000
#define MAXE 800000
#define CDIM 128

// Scratch (device globals: allocation-free rule). Everything batched over 2N/2E.
__device__ uint2  g_h[TT * MAXN * 32];          // 25.6 MB (GEMM product, fp16 rows, 2N)
__device__ float4 g_agg[TT * MAXN * (CDIM/4)];  // 51.2 MB (conv1 aggregation, fp32, 2N)
__device__ float  g_dinv[TT * MAXN];            // rsqrt(1 + deg)
__device__ int    g_hist[TT * MAXN];            // per-dst degree histogram
__device__ int    g_rowptr[TT * MAXN + 1];      // CSR row offsets (concatenated)
__device__ int    g_cursor[TT * MAXN];          // fill cursors for permute
__device__ int    g_csr_src[TT * MAXE];         // GLOBAL src id (t*N+s) per CSR slot
__device__ int    g_bsum[128];                  // per-1024-chunk sums for scan
__device__ int    g_is64;                       // 1 if input edge dtype is int64

// ---------------------------------------------------------------------------
// Edge-index dtype detection (raw buffer may be int32 or int64)
// ---------------------------------------------------------------------------
__global__ void k_detect(const unsigned int* __restrict__ raw, int total_elems) {
    if (blockIdx.x == 0 && threadIdx.x == 0) {
        int n = total_elems < 64 ? total_elems : 64;
        int all0 = 1;
        for (int i = 0; i < n; i++)
            if (raw[2 * i + 1] != 0u) { all0 = 0; break; }
        g_is64 = all0;
    }
}

__device__ __forceinline__ int load_idx(const unsigned int* raw, int pos, int is64) {
    return is64 ? (int)raw[2 * (size_t)pos] : (int)raw[pos];
}

// ---------------------------------------------------------------------------
// Batched CSR build (both timesteps): zero, hist, 3-stage scan(+dinv), permute
// All read the RAW edge buffer directly (no int32 materialization pass).
// ---------------------------------------------------------------------------
__global__ void k_zero(int* p, int n) {
    int i = blockIdx.x * blockDim.x + threadIdx.x;
    if (i < n) p[i] = 0;
}

__global__ void k_hist2(int* __restrict__ hist, const unsigned int* __restrict__ raw,
                        int E, int N) {
    int i = blockIdx.x * blockDim.x + threadIdx.x;
    if (i >= 2 * E) return;
    const int is64 = g_is64;
    const int t = (i >= E) ? 1 : 0;
    const int eid = i - t * E;
    const int d = load_idx(raw, t * 2 * E + E + eid, is64);
    atomicAdd(&hist[t * N + d], 1);
}

// Stage 1: per-1024-chunk sums.
__global__ __launch_bounds__(256) void k_bsum(const int* __restrict__ hist,
                                              int* __restrict__ bsum, int n) {
    __shared__ int ws[8];
    const int tid = threadIdx.x;
    const int base = blockIdx.x * 1024;
    int s = 0;
#pragma unroll
    for (int k = 0; k < 4; k++) {
        int i = base + k * 256 + tid;
        if (i < n) s += hist[i];
    }
#pragma unroll
    for (int o = 16; o; o >>= 1) s += __shfl_xor_sync(0xffffffffu, s, o);
    if ((tid & 31) == 0) ws[tid >> 5] = s;
    __syncthreads();
    if (tid < 32) {
        int v = (tid < 8) ? ws[tid] : 0;
#pragma unroll
        for (int o = 4; o; o >>= 1) v += __shfl_xor_sync(0xffffffffu, v, o);
        if (tid == 0) bsum[blockIdx.x] = v;
    }
}

// Stage 2: exclusive scan of <=128 chunk sums; writes rowptr[n2] = total.
__global__ __launch_bounds__(128) void k_scanb(int* __restrict__ bsum,
                                               int* __restrict__ rowptr,
                                               int nb, int n2) {
    __shared__ int ws[4];
    const int tid = threadIdx.x, lane = tid & 31, wid = tid >> 5;
    int v = (tid < nb) ? bsum[tid] : 0;
    int x = v;
#pragma unroll
    for (int o = 1; o < 32; o <<= 1) {
        int u = __shfl_up_sync(0xffffffffu, x, o);
        if (lane >= o) x += u;
    }
    if (lane == 31) ws[wid] = x;
    __syncthreads();
    if (wid == 0) {
        int wv = (lane < 4) ? ws[lane] : 0;
        int y = wv;
#pragma unroll
        for (int o = 1; o < 4; o <<= 1) {
            int u = __shfl_up_sync(0xffffffffu, y, o);
            if (lane >= o) y += u;
        }
        if (lane < 4) ws[lane] = y - wv;
    }
    __syncthreads();
    const int excl = x - v + ws[wid];
    if (tid < nb) bsum[tid] = excl;
    if (tid == nb - 1) rowptr[n2] = excl + v;
}

// Stage 3: per-chunk rescan + offset -> rowptr, cursor; fused dinv.
__global__ __launch_bounds__(256) void k_rowptr(const int* __restrict__ hist,
                                                const int* __restrict__ boff,
                                                int* __restrict__ rowptr,
                                                int* __restrict__ cursor,
                                                float* __restrict__ dinv, int n) {
    __shared__ int wsum[8];
    const int tid = threadIdx.x, lane = tid & 31, wid = tid >> 5;
    const int i0 = blockIdx.x * 1024 + tid * 4;
    int v0 = (i0     < n) ? hist[i0]     : 0;
    int v1 = (i0 + 1 < n) ? hist[i0 + 1] : 0;
    int v2 = (i0 + 2 < n) ? hist[i0 + 2] : 0;
    int v3 = (i0 + 3 < n) ? hist[i0 + 3] : 0;
    const int t = v0 + v1 + v2 + v3;
    int x = t;
#pragma unroll
    for (int o = 1; o < 32; o <<= 1) {
        int u = __shfl_up_sync(0xffffffffu, x, o);
        if (lane >= o) x += u;
    }
    if (lane == 31) wsum[wid] = x;
    __syncthreads();
    if (wid == 0) {
        int wv = (lane < 8) ? wsum[lane] : 0;
        int y = wv;
#pragma unroll
        for (int o = 1; o < 8; o <<= 1) {
            int u = __shfl_up_sync(0xffffffffu, y, o);
            if (lane >= o) y += u;
        }
        if (lane < 8) wsum[lane] = y - wv;
    }
    __syncthreads();
    int e0 = (x - t) + wsum[wid] + boff[blockIdx.x];
    int e1 = e0 + v0, e2 = e1 + v1, e3 = e2 + v2;
    if (i0     < n) { rowptr[i0]     = e0; cursor[i0]     = e0; dinv[i0]     = rsqrtf(1.0f + (float)v0); }
    if (i0 + 1 < n) { rowptr[i0 + 1] = e1; cursor[i0 + 1] = e1; dinv[i0 + 1] = rsqrtf(1.0f + (float)v1); }
    if (i0 + 2 < n) { rowptr[i0 + 2] = e2; cursor[i0 + 2] = e2; dinv[i0 + 2] = rsqrtf(1.0f + (float)v2); }
    if (i0 + 3 < n) { rowptr[i0 + 3] = e3; cursor[i0 + 3] = e3; dinv[i0 + 3] = rsqrtf(1.0f + (float)v3); }
}

// Permute: csr_src gets GLOBAL src id (t*N + s) so gathers are t-agnostic.
__global__ void k_permute2(const unsigned int* __restrict__ raw, int* __restrict__ cursor,
                           int* __restrict__ csr_src, int E, int N) {
    int i = blockIdx.x * blockDim.x + threadIdx.x;
    if (i >= 2 * E) return;
    const int is64 = g_is64;
    const int t = (i >= E) ? 1 : 0;
    const int eid = i - t * E;
    const int s = load_idx(raw, t * 2 * E + eid, is64);
    const int d = load_idx(raw, t * 2 * E + E + eid, is64);
    const int pos = atomicAdd(&cursor[t * N + d], 1);
    csr_src[pos] = t * N + s;
}

// ---------------------------------------------------------------------------
// Tensor-core GEMM: Yh[n,128] (fp16) = f(X)[n,128] (fp32) @ W[128,128]
// bf16 2-way split (3 MMA terms). mode 0: f(x)=x   mode 1: f(x)=relu(x+bias)
// ---------------------------------------------------------------------------
#define SPAD 136
#define GEMM_SMEM (4 * 128 * SPAD * 2)

__device__ __forceinline__ void store_split(__nv_bfloat16* H, __nv_bfloat16* L,
                                            int off, float4 v) {
    __nv_bfloat16 h0 = __float2bfloat16(v.x);
    __nv_bfloat16 h1 = __float2bfloat16(v.y);
    __nv_bfloat16 h2 = __float2bfloat16(v.z);
    __nv_bfloat16 h3 = __float2bfloat16(v.w);
    __nv_bfloat16 l0 = __float2bfloat16(v.x - __bfloat162float(h0));
    __nv_bfloat16 l1 = __float2bfloat16(v.y - __bfloat162float(h1));
    __nv_bfloat16 l2 = __float2bfloat16(v.z - __bfloat162float(h2));
    __nv_bfloat16 l3 = __float2bfloat16(v.w - __bfloat162float(h3));
    uint2 ph, pl;
    ph.x = (uint32_t)__bfloat16_as_ushort(h0) | ((uint32_t)__bfloat16_as_ushort(h1) << 16);
    ph.y = (uint32_t)__bfloat16_as_ushort(h2) | ((uint32_t)__bfloat16_as_ushort(h3) << 16);
    pl.x = (uint32_t)__bfloat16_as_ushort(l0) | ((uint32_t)__bfloat16_as_ushort(l1) << 16);
    pl.y = (uint32_t)__bfloat16_as_ushort(l2) | ((uint32_t)__bfloat16_as_ushort(l3) << 16);
    *reinterpret_cast<uint2*>(H + off) = ph;
    *reinterpret_cast<uint2*>(L + off) = pl;
}

#define LDSM_X4(r0, r1, r2, r3, addr)                                          \
    asm volatile("ldmatrix.sync.aligned.m8n8.x4.shared.b16 {%0,%1,%2,%3}, [%4];" \
                 : "=r"(r0), "=r"(r1), "=r"(r2), "=r"(r3) : "r"(addr))

#define LDSM_X4T(r0, r1, r2, r3, addr)                                         \
    asm volatile("ldmatrix.sync.aligned.m8n8.x4.trans.shared.b16 {%0,%1,%2,%3}, [%4];" \
                 : "=r"(r0), "=r"(r1), "=r"(r2), "=r"(r3) : "r"(addr))

#define MMA16816(C, a0, a1, a2, a3, b0, b1)                                    \
    asm volatile("mma.sync.aligned.m16n8k16.row.col.f32.bf16.bf16.f32 "        \
                 "{%0,%1,%2,%3}, {%4,%5,%6,%7}, {%8,%9}, {%0,%1,%2,%3};"       \
                 : "+f"(C[0]), "+f"(C[1]), "+f"(C[2]), "+f"(C[3])              \
                 : "r"(a0), "r"(a1), "r"(a2), "r"(a3), "r"(b0), "r"(b1))

__global__ __launch_bounds__(256) void k_gemm_mma(
    const float* __restrict__ X, const float* __restrict__ W,
    const float* __restrict__ bias, __half* __restrict__ Y, int nrows, int mode)
{
    extern __shared__ __nv_bfloat16 sm[];
    __nv_bfloat16* Ah = sm;
    __nv_bfloat16* Al = Ah + 128 * SPAD;
    __nv_bfloat16* Wh = Al + 128 * SPAD;
    __nv_bfloat16* Wl = Wh + 128 * SPAD;

    const int tid = threadIdx.x;
    const int lane = tid & 31, wid = tid >> 5;
    const int rowBase = blockIdx.x * 128;

#pragma unroll
    for (int it = 0; it < 16; it++) {
        const int idx = it * 256 + tid;
        const int row = idx >> 5;
        const int c4  = idx & 31;
        const float4 v = reinterpret_cast<const float4*>(W)[idx];
        store_split(Wh, Wl, row * SPAD + c4 * 4, v);
    }
#pragma unroll
    for (int it = 0; it < 16; it++) {
        const int idx = it * 256 + tid;
        const int row = idx >> 5;
        const int c4  = idx & 31;
        const int grow = rowBase + row;
        float4 v = make_float4(0.f, 0.f, 0.f, 0.f);
        if (grow < nrows) v = reinterpret_cast<const float4*>(X)[grow * 32 + c4];
        if (mode == 1) {
            const float4 b = reinterpret_cast<const float4*>(bias)[c4];
            v.x = fmaxf(v.x + b.x, 0.f);
            v.y = fmaxf(v.y + b.y, 0.f);
            v.z = fmaxf(v.z + b.z, 0.f);
            v.w = fmaxf(v.w + b.w, 0.f);
        }
        store_split(Ah, Al, row * SPAD + c4 * 4, v);
    }
    __syncthreads();

    const uint32_t sb = (uint32_t)__cvta_generic_to_shared(sm);
    const uint32_t HALF = 128 * SPAD * 2;
    const int sub = lane >> 3, li = lane & 7;
    const int arow = wid * 16 + ((sub & 1) << 3) + li;
    const int acol0 = (sub >> 1) << 3;
    const int bkrow0 = ((sub & 1) << 3) + li;
    const int bncol0 = (sub >> 1) << 3;

    float acc[16][4];
#pragma unroll
    for (int t = 0; t < 16; t++)
#pragma unroll
        for (int c = 0; c < 4; c++) acc[t][c] = 0.f;

    for (int k0 = 0; k0 < 128; k0 += 16) {
        uint32_t aaddr = sb + (uint32_t)((arow * SPAD + k0 + acol0) * 2);
        uint32_t ah0, ah1, ah2, ah3, al0, al1, al2, al3;
        LDSM_X4(ah0, ah1, ah2, ah3, aaddr);
        LDSM_X4(al0, al1, al2, al3, aaddr + HALF);

#pragma unroll
        for (int np = 0; np < 8; np++) {
            const int n0 = np * 16;
            uint32_t baddr = sb + 2u * HALF +
                (uint32_t)(((k0 + bkrow0) * SPAD + n0 + bncol0) * 2);
            uint32_t bh0, bh1, bh2, bh3, bl0, bl1, bl2, bl3;
            LDSM_X4T(bh0, bh1, bh2, bh3, baddr);
            LDSM_X4T(bl0, bl1, bl2, bl3, baddr + HALF);
            const int t0 = np * 2, t1 = t0 + 1;
            MMA16816(acc[t0], ah0, ah1, ah2, ah3, bh0, bh1);
            MMA16816(acc[t0], al0, al1, al2, al3, bh0, bh1);
            MMA16816(acc[t0], ah0, ah1, ah2, ah3, bl0, bl1);
            MMA16816(acc[t1], ah0, ah1, ah2, ah3, bh2, bh3);
            MMA16816(acc[t1], al0, al1, al2, al3, bh2, bh3);
            MMA16816(acc[t1], ah0, ah1, ah2, ah3, bl2, bl3);
        }
    }

    const int r0 = rowBase + wid * 16 + (lane >> 2);
    const int c0 = (lane & 3) * 2;
#pragma unroll
    for (int nt = 0; nt < 16; nt++) {
        const int col = nt * 8 + c0;
        if (r0 < nrows)
            *reinterpret_cast<__half2*>(&Y[r0 * 128 + col]) =
                __floats2half2_rn(acc[nt][0], acc[nt][1]);
        if (r0 + 8 < nrows)
            *reinterpret_cast<__half2*>(&Y[(r0 + 8) * 128 + col]) =
                __floats2half2_rn(acc[nt][2], acc[nt][3]);
    }
}

// ---------------------------------------------------------------------------
// CSR gather over ALL 2N nodes: one warp per node, fp16 rows, unroll x8.
//   out[g] = sum_{s in N(g)} h[s]*dinv[s]*dinv[g] + h[g]*dinv[g]^2 (+ bias)
// csr_src holds global ids, so no timestep handling needed here.
// ---------------------------------------------------------------------------
__device__ __forceinline__ float4 h4_to_f4(uint2 u) {
    const __half2 a = *reinterpret_cast<__half2*>(&u.x);
    const __half2 b = *reinterpret_cast<__half2*>(&u.y);
    const float2 fa = __half22float2(a), fb = __half22float2(b);
    return make_float4(fa.x, fa.y, fb.x, fb.y);
}

#define GFMA(A, V, W) \
    A.x = fmaf(V.x, W, A.x); A.y = fmaf(V.y, W, A.y); \
    A.z = fmaf(V.z, W, A.z); A.w = fmaf(V.w, W, A.w);

template <int MODE>
__global__ __launch_bounds__(256) void k_gather(
    const uint2* __restrict__ h, float4* __restrict__ out,
    const int* __restrict__ rowptr, const int* __restrict__ csr_src,
    const float* __restrict__ dinv, const float* __restrict__ bias, int n)
{
    const int node = blockIdx.x * 8 + (threadIdx.x >> 5);
    if (node >= n) return;
    const int lane = threadIdx.x & 31;

    const float dd = __ldg(&dinv[node]);
    const int js = __ldg(&rowptr[node]);
    const int je = __ldg(&rowptr[node + 1]);

    const float4 v = h4_to_f4(h[node * 32 + lane]);
    const float sl = dd * dd;
    float4 a0 = make_float4(v.x * sl, v.y * sl, v.z * sl, v.w * sl);
    float4 a1 = make_float4(0.f, 0.f, 0.f, 0.f);
    float4 a2 = make_float4(0.f, 0.f, 0.f, 0.f);
    float4 a3 = make_float4(0.f, 0.f, 0.f, 0.f);

    int j = js;
    for (; j + 7 < je; j += 8) {
        const int s0 = __ldg(&csr_src[j]);
        const int s1 = __ldg(&csr_src[j + 1]);
        const int s2 = __ldg(&csr_src[j + 2]);
        const int s3 = __ldg(&csr_src[j + 3]);
        const int s4 = __ldg(&csr_src[j + 4]);
        const int s5 = __ldg(&csr_src[j + 5]);
        const int s6 = __ldg(&csr_src[j + 6]);
        const int s7 = __ldg(&csr_src[j + 7]);
        const float w0 = dd * __ldg(&dinv[s0]);
        const float w1 = dd * __ldg(&dinv[s1]);
        const float w2 = dd * __ldg(&dinv[s2]);
        const float w3 = dd * __ldg(&dinv[s3]);
        const float w4 = dd * __ldg(&dinv[s4]);
        const float w5 = dd * __ldg(&dinv[s5]);
        const float w6 = dd * __ldg(&dinv[s6]);
        const float w7 = dd * __ldg(&dinv[s7]);
        const float4 v0 = h4_to_f4(h[s0 * 32 + lane]);
        const float4 v1 = h4_to_f4(h[s1 * 32 + lane]);
        const float4 v2 = h4_to_f4(h[s2 * 32 + lane]);
        const float4 v3 = h4_to_f4(h[s3 * 32 + lane]);
        const float4 v4 = h4_to_f4(h[s4 * 32 + lane]);
        const float4 v5 = h4_to_f4(h[s5 * 32 + lane]);
        const float4 v6 = h4_to_f4(h[s6 * 32 + lane]);
        const float4 v7 = h4_to_f4(h[s7 * 32 + lane]);
        GFMA(a0, v0, w0); GFMA(a1, v1, w1); GFMA(a2, v2, w2); GFMA(a3, v3, w3);
        GFMA(a0, v4, w4); GFMA(a1, v5, w5); GFMA(a2, v6, w6); GFMA(a3, v7, w7);
    }
    for (; j + 3 < je; j += 4) {
        const int s0 = __ldg(&csr_src[j]);
        const int s1 = __ldg(&csr_src[j + 1]);
        const int s2 = __ldg(&csr_src[j + 2]);
        const int s3 = __ldg(&csr_src[j + 3]);
        const float w0 = dd * __ldg(&dinv[s0]);
        const float w1 = dd * __ldg(&dinv[s1]);
        const float w2 = dd * __ldg(&dinv[s2]);
        const float w3 = dd * __ldg(&dinv[s3]);
        const float4 v0 = h4_to_f4(h[s0 * 32 + lane]);
        const float4 v1 = h4_to_f4(h[s1 * 32 + lane]);
        const float4 v2 = h4_to_f4(h[s2 * 32 + lane]);
        const float4 v3 = h4_to_f4(h[s3 * 32 + lane]);
        GFMA(a0, v0, w0); GFMA(a1, v1, w1); GFMA(a2, v2, w2); GFMA(a3, v3, w3);
    }
    for (; j < je; j++) {
        const int s0 = __ldg(&csr_src[j]);
        const float w0 = dd * __ldg(&dinv[s0]);
        const float4 v0 = h4_to_f4(h[s0 * 32 + lane]);
        GFMA(a0, v0, w0);
    }
    a0.x += a1.x + a2.x + a3.x;
    a0.y += a1.y + a2.y + a3.y;
    a0.z += a1.z + a2.z + a3.z;
    a0.w += a1.w + a2.w + a3.w;

    if (MODE == 1) {
        const float4 b = reinterpret_cast<const float4*>(bias)[lane];
        a0.x += b.x; a0.y += b.y; a0.z += b.z; a0.w += b.w;
    }
    out[node * 32 + lane] = a0;
}

// ---------------------------------------------------------------------------
// Importance: imp[n] = dot(out1[n,:], Wc) + bc   (one warp per node)
// ---------------------------------------------------------------------------
__global__ void k_importance(const float* __restrict__ out1, const float* __restrict__ Wc,
                             const float* __restrict__ bc, float* __restrict__ imp, int n)
{
    const int node = (int)((blockIdx.x * blockDim.x + threadIdx.x) >> 5);
    if (node >= n) return;
    const int lane = threadIdx.x & 31;
    const float4 a = reinterpret_cast<const float4*>(out1)[node * 32 + lane];
    const float4 w = reinterpret_cast<const float4*>(Wc)[lane];
    float s = a.x * w.x + a.y * w.y + a.z * w.z + a.w * w.w;
#pragma unroll
    for (int off = 16; off; off >>= 1) s += __shfl_xor_sync(0xffffffffu, s, off);
    if (lane == 0) imp[node] = s + bc[0];
}

// ---------------------------------------------------------------------------
// Launch — fully batched over both timesteps
// ---------------------------------------------------------------------------
extern "C" void kernel_launch(void* const* d_in, const int* in_sizes, int n_in,
                              void* d_out, int out_size)
{
    const float*        x_seq = (const float*)d_in[0];        // [2N, 128] contiguous
    const unsigned int* eraw  = (const unsigned int*)d_in[1]; // [T, 2, E] int32 or int64
    const float*        W1    = (const float*)d_in[2];
    const float*        b1    = (const float*)d_in[3];
    const float*        W2    = (const float*)d_in[4];
    const float*        b2    = (const float*)d_in[5];
    const float*        Wc    = (const float*)d_in[6];
    const float*        bc    = (const float*)d_in[7];

    const int N = in_sizes[0] / (TT * CDIM);
    const int E = in_sizes[1] / (TT * 2);
    const int totalE = TT * 2 * E;
    const int n2 = TT * N;

    float* out  = (float*)d_out;
    float* imp  = out;          // [N]
    float* outs = out + N;      // [2N,128] contiguous (out_t0 then out_t1)

    uint2* dh;  float4* dagg;  float* ddinv;
    int* dhist;  int* drowptr;  int* dcursor;  int* dcsr;  int* dbsum;
    cudaGetSymbolAddress((void**)&dh,      g_h);
    cudaGetSymbolAddress((void**)&dagg,    g_agg);
    cudaGetSymbolAddress((void**)&ddinv,   g_dinv);
    cudaGetSymbolAddress((void**)&dhist,   g_hist);
    cudaGetSymbolAddress((void**)&drowptr, g_rowptr);
    cudaGetSymbolAddress((void**)&dcursor, g_cursor);
    cudaGetSymbolAddress((void**)&dcsr,    g_csr_src);
    cudaGetSymbolAddress((void**)&dbsum,   g_bsum);

    cudaFuncSetAttribute(k_gemm_mma, cudaFuncAttributeMaxDynamicSharedMemorySize,
                         GEMM_SMEM);

    const int TPB = 256;
    const int gGemm = (n2 + 127) / 128;
    const int gGath = (n2 + 7) / 8;
    const int g2E   = (2 * E + TPB - 1) / TPB;
    const int g2N   = (n2 + TPB - 1) / TPB;
    const int nb    = (n2 + 1023) / 1024;

    // Edge dtype probe + batched CSR build (both timesteps at once).
    k_detect<<<1, 32>>>(eraw, totalE);
    k_zero<<<g2N, TPB>>>(dhist, n2);
    k_hist2<<<g2E, TPB>>>(dhist, eraw, E, N);
    k_bsum<<<nb, TPB>>>(dhist, dbsum, n2);
    k_scanb<<<1, 128>>>(dbsum, drowptr, nb, n2);
    k_rowptr<<<nb, TPB>>>(dhist, dbsum, drowptr, dcursor, ddinv, n2);
    k_permute2<<<g2E, TPB>>>(eraw, dcursor, dcsr, E, N);

    // conv1 (both timesteps): h = x @ W1 (fp16) ; agg = gather(h) (fp32)
    k_gemm_mma<<<gGemm, TPB, GEMM_SMEM>>>(x_seq, W1, b1, (__half*)dh, n2, 0);
    k_gather<0><<<gGath, TPB>>>(dh, dagg, drowptr, dcsr, ddinv, b1, n2);

    // conv2 (both timesteps): h = relu(agg+b1) @ W2 (fp16) ; outs = gather(h)+b2
    k_gemm_mma<<<gGemm, TPB, GEMM_SMEM>>>((const float*)dagg, W2, b1, (__half*)dh, n2, 1);
    k_gather<1><<<gGath, TPB>>>(dh, (float4*)outs, drowptr, dcsr, ddinv, b2, n2);

    // importance from last timestep's output
    k_importance<<<(N * 32 + TPB - 1) / TPB, TPB>>>(outs + (size_t)(TT - 1) * N * CDIM,
                                                    Wc, bc, imp, N);
}

// round 11
// speedup vs baseline: 2.6014x; 1.1247x over previous
#include <cuda_runtime.h>
#include <cuda_bf16.h>
#include <cuda_fp16.h>
#include <cstdint>

// Problem constants (from reference): T=2, N=50000, E=800000, C=128
#define TT 2
#define MAXN 50000
#define MAXE 800000
#define CDIM 128

// Scratch (device globals: allocation-free rule). Everything batched over 2N/2E.
__device__ uint2  g_h[TT * MAXN * 32];          // 25.6 MB (GEMM product, fp16 rows, 2N)
__device__ float4 g_agg[TT * MAXN * (CDIM/4)];  // 51.2 MB (conv1 aggregation, fp32, 2N)
__device__ float  g_dinv[TT * MAXN];            // rsqrt(1 + deg)
__device__ int    g_hist[TT * MAXN];            // per-dst degree histogram
__device__ int    g_rowptr[TT * MAXN + 1];      // CSR row offsets (concatenated)
__device__ int    g_cursor[TT * MAXN];          // fill cursors for permute
__device__ int    g_csr_src[TT * MAXE];         // GLOBAL src id (t*N+s) per CSR slot
__device__ int    g_bsum[128];                  // per-1024-chunk sums for scan
__device__ int    g_is64;                       // 1 if input edge dtype is int64
__device__ __nv_bfloat16 g_wh[2][CDIM * CDIM];  // pre-split W (high)
__device__ __nv_bfloat16 g_wl[2][CDIM * CDIM];  // pre-split W (low)

// ---------------------------------------------------------------------------
// Edge-index dtype detection (raw buffer may be int32 or int64)
// ---------------------------------------------------------------------------
__global__ void k_detect(const unsigned int* __restrict__ raw, int total_elems) {
    if (blockIdx.x == 0 && threadIdx.x == 0) {
        int n = total_elems < 64 ? total_elems : 64;
        int all0 = 1;
        for (int i = 0; i < n; i++)
            if (raw[2 * i + 1] != 0u) { all0 = 0; break; }
        g_is64 = all0;
    }
}

__device__ __forceinline__ int load_idx(const unsigned int* raw, int pos, int is64) {
    return is64 ? (int)raw[2 * (size_t)pos] : (int)raw[pos];
}

// ---------------------------------------------------------------------------
// W split: W (f32) -> Wh + Wl (bf16), done once per weight matrix.
// ---------------------------------------------------------------------------
__global__ void k_wsplit(const float* __restrict__ W, __nv_bfloat16* __restrict__ H,
                         __nv_bfloat16* __restrict__ L) {
    const int i = blockIdx.x * blockDim.x + threadIdx.x;  // 16384 threads total
    const float v = W[i];
    const __nv_bfloat16 h = __float2bfloat16(v);
    H[i] = h;
    L[i] = __float2bfloat16(v - __bfloat162float(h));
}

// ---------------------------------------------------------------------------
// Batched CSR build (both timesteps)
// ---------------------------------------------------------------------------
__global__ void k_zero(int* p, int n) {
    int i = blockIdx.x * blockDim.x + threadIdx.x;
    if (i < n) p[i] = 0;
}

__global__ void k_hist2(int* __restrict__ hist, const unsigned int* __restrict__ raw,
                        int E, int N) {
    int i = blockIdx.x * blockDim.x + threadIdx.x;
    if (i >= 2 * E) return;
    const int is64 = g_is64;
    const int t = (i >= E) ? 1 : 0;
    const int eid = i - t * E;
    const int d = load_idx(raw, t * 2 * E + E + eid, is64);
    atomicAdd(&hist[t * N + d], 1);
}

__global__ __launch_bounds__(256) void k_bsum(const int* __restrict__ hist,
                                              int* __restrict__ bsum, int n) {
    __shared__ int ws[8];
    const int tid = threadIdx.x;
    const int base = blockIdx.x * 1024;
    int s = 0;
#pragma unroll
    for (int k = 0; k < 4; k++) {
        int i = base + k * 256 + tid;
        if (i < n) s += hist[i];
    }
#pragma unroll
    for (int o = 16; o; o >>= 1) s += __shfl_xor_sync(0xffffffffu, s, o);
    if ((tid & 31) == 0) ws[tid >> 5] = s;
    __syncthreads();
    if (tid < 32) {
        int v = (tid < 8) ? ws[tid] : 0;
#pragma unroll
        for (int o = 4; o; o >>= 1) v += __shfl_xor_sync(0xffffffffu, v, o);
        if (tid == 0) bsum[blockIdx.x] = v;
    }
}

__global__ __launch_bounds__(128) void k_scanb(int* __restrict__ bsum,
                                               int* __restrict__ rowptr,
                                               int nb, int n2) {
    __shared__ int ws[4];
    const int tid = threadIdx.x, lane = tid & 31, wid = tid >> 5;
    int v = (tid < nb) ? bsum[tid] : 0;
    int x = v;
#pragma unroll
    for (int o = 1; o < 32; o <<= 1) {
        int u = __shfl_up_sync(0xffffffffu, x, o);
        if (lane >= o) x += u;
    }
    if (lane == 31) ws[wid] = x;
    __syncthreads();
    if (wid == 0) {
        int wv = (lane < 4) ? ws[lane] : 0;
        int y = wv;
#pragma unroll
        for (int o = 1; o < 4; o <<= 1) {
            int u = __shfl_up_sync(0xffffffffu, y, o);
            if (lane >= o) y += u;
        }
        if (lane < 4) ws[lane] = y - wv;
    }
    __syncthreads();
    const int excl = x - v + ws[wid];
    if (tid < nb) bsum[tid] = excl;
    if (tid == nb - 1) rowptr[n2] = excl + v;
}

__global__ __launch_bounds__(256) void k_rowptr(const int* __restrict__ hist,
                                                const int* __restrict__ boff,
                                                int* __restrict__ rowptr,
                                                int* __restrict__ cursor,
                                                float* __restrict__ dinv, int n) {
    __shared__ int wsum[8];
    const int tid = threadIdx.x, lane = tid & 31, wid = tid >> 5;
    const int i0 = blockIdx.x * 1024 + tid * 4;
    int v0 = (i0     < n) ? hist[i0]     : 0;
    int v1 = (i0 + 1 < n) ? hist[i0 + 1] : 0;
    int v2 = (i0 + 2 < n) ? hist[i0 + 2] : 0;
    int v3 = (i0 + 3 < n) ? hist[i0 + 3] : 0;
    const int t = v0 + v1 + v2 + v3;
    int x = t;
#pragma unroll
    for (int o = 1; o < 32; o <<= 1) {
        int u = __shfl_up_sync(0xffffffffu, x, o);
        if (lane >= o) x += u;
    }
    if (lane == 31) wsum[wid] = x;
    __syncthreads();
    if (wid == 0) {
        int wv = (lane < 8) ? wsum[lane] : 0;
        int y = wv;
#pragma unroll
        for (int o = 1; o < 8; o <<= 1) {
            int u = __shfl_up_sync(0xffffffffu, y, o);
            if (lane >= o) y += u;
        }
        if (lane < 8) wsum[lane] = y - wv;
    }
    __syncthreads();
    int e0 = (x - t) + wsum[wid] + boff[blockIdx.x];
    int e1 = e0 + v0, e2 = e1 + v1, e3 = e2 + v2;
    if (i0     < n) { rowptr[i0]     = e0; cursor[i0]     = e0; dinv[i0]     = rsqrtf(1.0f + (float)v0); }
    if (i0 + 1 < n) { rowptr[i0 + 1] = e1; cursor[i0 + 1] = e1; dinv[i0 + 1] = rsqrtf(1.0f + (float)v1); }
    if (i0 + 2 < n) { rowptr[i0 + 2] = e2; cursor[i0 + 2] = e2; dinv[i0 + 2] = rsqrtf(1.0f + (float)v2); }
    if (i0 + 3 < n) { rowptr[i0 + 3] = e3; cursor[i0 + 3] = e3; dinv[i0 + 3] = rsqrtf(1.0f + (float)v3); }
}

__global__ void k_permute2(const unsigned int* __restrict__ raw, int* __restrict__ cursor,
                           int* __restrict__ csr_src, int E, int N) {
    int i = blockIdx.x * blockDim.x + threadIdx.x;
    if (i >= 2 * E) return;
    const int is64 = g_is64;
    const int t = (i >= E) ? 1 : 0;
    const int eid = i - t * E;
    const int s = load_idx(raw, t * 2 * E + eid, is64);
    const int d = load_idx(raw, t * 2 * E + E + eid, is64);
    const int pos = atomicAdd(&cursor[t * N + d], 1);
    csr_src[pos] = t * N + s;
}

// ---------------------------------------------------------------------------
// Tensor-core GEMM: Yh[n,128] (fp16) = f(X)[n,128] (fp32) @ W[128,128]
// bf16 2-way split (3 MMA terms). W pre-split in global (bf16 Wh/Wl).
// M-tile 64 (8 warps as 4x2): smem 104 KB -> 2 blocks/SM for latency hiding.
// ---------------------------------------------------------------------------
#define SPAD 136
#define GEMM_SMEM ((2 * 64 + 2 * 128) * SPAD * 2)

__device__ __forceinline__ void store_split_a(__nv_bfloat16* H, __nv_bfloat16* L,
                                              int off, float4 v) {
    __nv_bfloat16 h0 = __float2bfloat16(v.x);
    __nv_bfloat16 h1 = __float2bfloat16(v.y);
    __nv_bfloat16 h2 = __float2bfloat16(v.z);
    __nv_bfloat16 h3 = __float2bfloat16(v.w);
    __nv_bfloat16 l0 = __float2bfloat16(v.x - __bfloat162float(h0));
    __nv_bfloat16 l1 = __float2bfloat16(v.y - __bfloat162float(h1));
    __nv_bfloat16 l2 = __float2bfloat16(v.z - __bfloat162float(h2));
    __nv_bfloat16 l3 = __float2bfloat16(v.w - __bfloat162float(h3));
    uint2 ph, pl;
    ph.x = (uint32_t)__bfloat16_as_ushort(h0) | ((uint32_t)__bfloat16_as_ushort(h1) << 16);
    ph.y = (uint32_t)__bfloat16_as_ushort(h2) | ((uint32_t)__bfloat16_as_ushort(h3) << 16);
    pl.x = (uint32_t)__bfloat16_as_ushort(l0) | ((uint32_t)__bfloat16_as_ushort(l1) << 16);
    pl.y = (uint32_t)__bfloat16_as_ushort(l2) | ((uint32_t)__bfloat16_as_ushort(l3) << 16);
    *reinterpret_cast<uint2*>(H + off) = ph;
    *reinterpret_cast<uint2*>(L + off) = pl;
}

#define LDSM_X4(r0, r1, r2, r3, addr)                                          \
    asm volatile("ldmatrix.sync.aligned.m8n8.x4.shared.b16 {%0,%1,%2,%3}, [%4];" \
                 : "=r"(r0), "=r"(r1), "=r"(r2), "=r"(r3) : "r"(addr))

#define LDSM_X4T(r0, r1, r2, r3, addr)                                         \
    asm volatile("ldmatrix.sync.aligned.m8n8.x4.trans.shared.b16 {%0,%1,%2,%3}, [%4];" \
                 : "=r"(r0), "=r"(r1), "=r"(r2), "=r"(r3) : "r"(addr))

#define MMA16816(C, a0, a1, a2, a3, b0, b1)                                    \
    asm volatile("mma.sync.aligned.m16n8k16.row.col.f32.bf16.bf16.f32 "        \
                 "{%0,%1,%2,%3}, {%4,%5,%6,%7}, {%8,%9}, {%0,%1,%2,%3};"       \
                 : "+f"(C[0]), "+f"(C[1]), "+f"(C[2]), "+f"(C[3])              \
                 : "r"(a0), "r"(a1), "r"(a2), "r"(a3), "r"(b0), "r"(b1))

__global__ __launch_bounds__(256) void k_gemm_mma(
    const float* __restrict__ X,
    const __nv_bfloat16* __restrict__ Whg, const __nv_bfloat16* __restrict__ Wlg,
    const float* __restrict__ bias, __half* __restrict__ Y, int nrows, int mode)
{
    extern __shared__ __nv_bfloat16 sm[];
    __nv_bfloat16* Ah = sm;                       //  64 x SPAD
    __nv_bfloat16* Al = Ah + 64 * SPAD;           //  64 x SPAD
    __nv_bfloat16* Wh = Al + 64 * SPAD;           // 128 x SPAD
    __nv_bfloat16* Wl = Wh + 128 * SPAD;          // 128 x SPAD

    const int tid = threadIdx.x;
    const int lane = tid & 31, wid = tid >> 5;
    const int rowBase = blockIdx.x * 64;

    // Load pre-split W (bf16, vectorized 8 at a time).
#pragma unroll
    for (int it = 0; it < 8; it++) {
        const int idx = it * 256 + tid;           // 2048 uint4 per array
        const int row = idx >> 4;
        const int c8  = (idx & 15) * 8;
        *reinterpret_cast<uint4*>(Wh + row * SPAD + c8) =
            reinterpret_cast<const uint4*>(Whg)[idx];
        *reinterpret_cast<uint4*>(Wl + row * SPAD + c8) =
            reinterpret_cast<const uint4*>(Wlg)[idx];
    }
    // Load + split X tile (64 rows).
#pragma unroll
    for (int it = 0; it < 8; it++) {
        const int idx = it * 256 + tid;           // 2048 float4
        const int row = idx >> 5;
        const int c4  = idx & 31;
        const int grow = rowBase + row;
        float4 v = make_float4(0.f, 0.f, 0.f, 0.f);
        if (grow < nrows) v = reinterpret_cast<const float4*>(X)[grow * 32 + c4];
        if (mode == 1) {
            const float4 b = reinterpret_cast<const float4*>(bias)[c4];
            v.x = fmaxf(v.x + b.x, 0.f);
            v.y = fmaxf(v.y + b.y, 0.f);
            v.z = fmaxf(v.z + b.z, 0.f);
            v.w = fmaxf(v.w + b.w, 0.f);
        }
        store_split_a(Ah, Al, row * SPAD + c4 * 4, v);
    }
    __syncthreads();

    const uint32_t sb = (uint32_t)__cvta_generic_to_shared(sm);
    const uint32_t AHALF = 64 * SPAD * 2;         // bytes Ah->Al
    const uint32_t WBASE = 2u * AHALF;            // byte offset of Wh
    const uint32_t WHALF = 128 * SPAD * 2;        // bytes Wh->Wl
    const int sub = lane >> 3, li = lane & 7;
    const int wm = wid & 3;                       // M tile (rows wm*16)
    const int wn = wid >> 2;                      // N half (cols wn*64)
    const int arow = wm * 16 + ((sub & 1) << 3) + li;
    const int acol0 = (sub >> 1) << 3;
    const int bkrow0 = ((sub & 1) << 3) + li;
    const int bncol0 = wn * 64 + ((sub >> 1) << 3);

    float acc[8][4];
#pragma unroll
    for (int t = 0; t < 8; t++)
#pragma unroll
        for (int c = 0; c < 4; c++) acc[t][c] = 0.f;

    for (int k0 = 0; k0 < 128; k0 += 16) {
        uint32_t aaddr = sb + (uint32_t)((arow * SPAD + k0 + acol0) * 2);
        uint32_t ah0, ah1, ah2, ah3, al0, al1, al2, al3;
        LDSM_X4(ah0, ah1, ah2, ah3, aaddr);
        LDSM_X4(al0, al1, al2, al3, aaddr + AHALF);

#pragma unroll
        for (int np = 0; np < 4; np++) {
            uint32_t baddr = sb + WBASE +
                (uint32_t)(((k0 + bkrow0) * SPAD + np * 16 + bncol0) * 2);
            uint32_t bh0, bh1, bh2, bh3, bl0, bl1, bl2, bl3;
            LDSM_X4T(bh0, bh1, bh2, bh3, baddr);
            LDSM_X4T(bl0, bl1, bl2, bl3, baddr + WHALF);
            const int t0 = np * 2, t1 = t0 + 1;
            MMA16816(acc[t0], ah0, ah1, ah2, ah3, bh0, bh1);
            MMA16816(acc[t0], al0, al1, al2, al3, bh0, bh1);
            MMA16816(acc[t0], ah0, ah1, ah2, ah3, bl0, bl1);
            MMA16816(acc[t1], ah0, ah1, ah2, ah3, bh2, bh3);
            MMA16816(acc[t1], al0, al1, al2, al3, bh2, bh3);
            MMA16816(acc[t1], ah0, ah1, ah2, ah3, bl2, bl3);
        }
    }

    const int r0 = rowBase + wm * 16 + (lane >> 2);
    const int c0 = wn * 64 + (lane & 3) * 2;
#pragma unroll
    for (int nt = 0; nt < 8; nt++) {
        const int col = c0 + nt * 8;
        if (r0 < nrows)
            *reinterpret_cast<__half2*>(&Y[r0 * 128 + col]) =
                __floats2half2_rn(acc[nt][0], acc[nt][1]);
        if (r0 + 8 < nrows)
            *reinterpret_cast<__half2*>(&Y[(r0 + 8) * 128 + col]) =
                __floats2half2_rn(acc[nt][2], acc[nt][3]);
    }
}

// ---------------------------------------------------------------------------
// CSR gather over ALL 2N nodes: one warp per node, fp16 rows, unroll x8.
// ---------------------------------------------------------------------------
__device__ __forceinline__ float4 h4_to_f4(uint2 u) {
    const __half2 a = *reinterpret_cast<__half2*>(&u.x);
    const __half2 b = *reinterpret_cast<__half2*>(&u.y);
    const float2 fa = __half22float2(a), fb = __half22float2(b);
    return make_float4(fa.x, fa.y, fb.x, fb.y);
}

#define GFMA(A, V, W) \
    A.x = fmaf(V.x, W, A.x); A.y = fmaf(V.y, W, A.y); \
    A.z = fmaf(V.z, W, A.z); A.w = fmaf(V.w, W, A.w);

template <int MODE>
__global__ __launch_bounds__(256) void k_gather(
    const uint2* __restrict__ h, float4* __restrict__ out,
    const int* __restrict__ rowptr, const int* __restrict__ csr_src,
    const float* __restrict__ dinv, const float* __restrict__ bias, int n)
{
    const int node = blockIdx.x * 8 + (threadIdx.x >> 5);
    if (node >= n) return;
    const int lane = threadIdx.x & 31;

    const float dd = __ldg(&dinv[node]);
    const int js = __ldg(&rowptr[node]);
    const int je = __ldg(&rowptr[node + 1]);

    const float4 v = h4_to_f4(h[node * 32 + lane]);
    const float sl = dd * dd;
    float4 a0 = make_float4(v.x * sl, v.y * sl, v.z * sl, v.w * sl);
    float4 a1 = make_float4(0.f, 0.f, 0.f, 0.f);
    float4 a2 = make_float4(0.f, 0.f, 0.f, 0.f);
    float4 a3 = make_float4(0.f, 0.f, 0.f, 0.f);

    int j = js;
    for (; j + 7 < je; j += 8) {
        const int s0 = __ldg(&csr_src[j]);
        const int s1 = __ldg(&csr_src[j + 1]);
        const int s2 = __ldg(&csr_src[j + 2]);
        const int s3 = __ldg(&csr_src[j + 3]);
        const int s4 = __ldg(&csr_src[j + 4]);
        const int s5 = __ldg(&csr_src[j + 5]);
        const int s6 = __ldg(&csr_src[j + 6]);
        const int s7 = __ldg(&csr_src[j + 7]);
        const float w0 = dd * __ldg(&dinv[s0]);
        const float w1 = dd * __ldg(&dinv[s1]);
        const float w2 = dd * __ldg(&dinv[s2]);
        const float w3 = dd * __ldg(&dinv[s3]);
        const float w4 = dd * __ldg(&dinv[s4]);
        const float w5 = dd * __ldg(&dinv[s5]);
        const float w6 = dd * __ldg(&dinv[s6]);
        const float w7 = dd * __ldg(&dinv[s7]);
        const float4 v0 = h4_to_f4(h[s0 * 32 + lane]);
        const float4 v1 = h4_to_f4(h[s1 * 32 + lane]);
        const float4 v2 = h4_to_f4(h[s2 * 32 + lane]);
        const float4 v3 = h4_to_f4(h[s3 * 32 + lane]);
        const float4 v4 = h4_to_f4(h[s4 * 32 + lane]);
        const float4 v5 = h4_to_f4(h[s5 * 32 + lane]);
        const float4 v6 = h4_to_f4(h[s6 * 32 + lane]);
        const float4 v7 = h4_to_f4(h[s7 * 32 + lane]);
        GFMA(a0, v0, w0); GFMA(a1, v1, w1); GFMA(a2, v2, w2); GFMA(a3, v3, w3);
        GFMA(a0, v4, w4); GFMA(a1, v5, w5); GFMA(a2, v6, w6); GFMA(a3, v7, w7);
    }
    for (; j + 3 < je; j += 4) {
        const int s0 = __ldg(&csr_src[j]);
        const int s1 = __ldg(&csr_src[j + 1]);
        const int s2 = __ldg(&csr_src[j + 2]);
        const int s3 = __ldg(&csr_src[j + 3]);
        const float w0 = dd * __ldg(&dinv[s0]);
        const float w1 = dd * __ldg(&dinv[s1]);
        const float w2 = dd * __ldg(&dinv[s2]);
        const float w3 = dd * __ldg(&dinv[s3]);
        const float4 v0 = h4_to_f4(h[s0 * 32 + lane]);
        const float4 v1 = h4_to_f4(h[s1 * 32 + lane]);
        const float4 v2 = h4_to_f4(h[s2 * 32 + lane]);
        const float4 v3 = h4_to_f4(h[s3 * 32 + lane]);
        GFMA(a0, v0, w0); GFMA(a1, v1, w1); GFMA(a2, v2, w2); GFMA(a3, v3, w3);
    }
    for (; j < je; j++) {
        const int s0 = __ldg(&csr_src[j]);
        const float w0 = dd * __ldg(&dinv[s0]);
        const float4 v0 = h4_to_f4(h[s0 * 32 + lane]);
        GFMA(a0, v0, w0);
    }
    a0.x += a1.x + a2.x + a3.x;
    a0.y += a1.y + a2.y + a3.y;
    a0.z += a1.z + a2.z + a3.z;
    a0.w += a1.w + a2.w + a3.w;

    if (MODE == 1) {
        const float4 b = reinterpret_cast<const float4*>(bias)[lane];
        a0.x += b.x; a0.y += b.y; a0.z += b.z; a0.w += b.w;
    }
    out[node * 32 + lane] = a0;
}

// ---------------------------------------------------------------------------
// Importance: imp[n] = dot(out1[n,:], Wc) + bc   (one warp per node)
// ---------------------------------------------------------------------------
__global__ void k_importance(const float* __restrict__ out1, const float* __restrict__ Wc,
                             const float* __restrict__ bc, float* __restrict__ imp, int n)
{
    const int node = (int)((blockIdx.x * blockDim.x + threadIdx.x) >> 5);
    if (node >= n) return;
    const int lane = threadIdx.x & 31;
    const float4 a = reinterpret_cast<const float4*>(out1)[node * 32 + lane];
    const float4 w = reinterpret_cast<const float4*>(Wc)[lane];
    float s = a.x * w.x + a.y * w.y + a.z * w.z + a.w * w.w;
#pragma unroll
    for (int off = 16; off; off >>= 1) s += __shfl_xor_sync(0xffffffffu, s, off);
    if (lane == 0) imp[node] = s + bc[0];
}

// ---------------------------------------------------------------------------
// Launch — batched over both timesteps; CSR build overlapped with GEMM1
// ---------------------------------------------------------------------------
extern "C" void kernel_launch(void* const* d_in, const int* in_sizes, int n_in,
                              void* d_out, int out_size)
{
    const float*        x_seq = (const float*)d_in[0];        // [2N, 128] contiguous
    const unsigned int* eraw  = (const unsigned int*)d_in[1]; // [T, 2, E] int32 or int64
    const float*        W1    = (const float*)d_in[2];
    const float*        b1    = (const float*)d_in[3];
    const float*        W2    = (const float*)d_in[4];
    const float*        b2    = (const float*)d_in[5];
    const float*        Wc    = (const float*)d_in[6];
    const float*        bc    = (const float*)d_in[7];

    const int N = in_sizes[0] / (TT * CDIM);
    const int E = in_sizes[1] / (TT * 2);
    const int totalE = TT * 2 * E;
    const int n2 = TT * N;

    float* out  = (float*)d_out;
    float* imp  = out;          // [N]
    float* outs = out + N;      // [2N,128] contiguous (out_t0 then out_t1)

    uint2* dh;  float4* dagg;  float* ddinv;
    int* dhist;  int* drowptr;  int* dcursor;  int* dcsr;  int* dbsum;
    __nv_bfloat16* dwh; __nv_bfloat16* dwl;
    cudaGetSymbolAddress((void**)&dh,      g_h);
    cudaGetSymbolAddress((void**)&dagg,    g_agg);
    cudaGetSymbolAddress((void**)&ddinv,   g_dinv);
    cudaGetSymbolAddress((void**)&dhist,   g_hist);
    cudaGetSymbolAddress((void**)&drowptr, g_rowptr);
    cudaGetSymbolAddress((void**)&dcursor, g_cursor);
    cudaGetSymbolAddress((void**)&dcsr,    g_csr_src);
    cudaGetSymbolAddress((void**)&dbsum,   g_bsum);
    cudaGetSymbolAddress((void**)&dwh,     g_wh);
    cudaGetSymbolAddress((void**)&dwl,     g_wl);

    static bool s_init = false;
    static cudaStream_t s_side = nullptr;
    static cudaEvent_t ev_fork = nullptr, ev_join = nullptr;
    if (!s_init) {
        cudaFuncSetAttribute(k_gemm_mma, cudaFuncAttributeMaxDynamicSharedMemorySize,
                             GEMM_SMEM);
        if (cudaStreamCreateWithFlags(&s_side, cudaStreamNonBlocking) != cudaSuccess)
            s_side = nullptr;
        if (s_side) {
            cudaEventCreateWithFlags(&ev_fork, cudaEventDisableTiming);
            cudaEventCreateWithFlags(&ev_join, cudaEventDisableTiming);
        }
        s_init = true;
    }

    const int TPB = 256;
    const int gGemm = (n2 + 63) / 64;
    const int gGath = (n2 + 7) / 8;
    const int g2E   = (2 * E + TPB - 1) / TPB;
    const int g2N   = (n2 + TPB - 1) / TPB;
    const int nb    = (n2 + 1023) / 1024;

    const bool fork = (s_side != nullptr);
    cudaStream_t sc = fork ? s_side : (cudaStream_t)0;   // CSR-build stream

    // Edge dtype probe first (CSR chain depends on it).
    k_detect<<<1, 32>>>(eraw, totalE);
    if (fork) {
        cudaEventRecord(ev_fork, 0);
        cudaStreamWaitEvent(s_side, ev_fork, 0);
    }

    // --- CSR build chain (side stream) ---
    k_zero<<<g2N, TPB, 0, sc>>>(dhist, n2);
    k_hist2<<<g2E, TPB, 0, sc>>>(dhist, eraw, E, N);
    k_bsum<<<nb, TPB, 0, sc>>>(dhist, dbsum, n2);
    k_scanb<<<1, 128, 0, sc>>>(dbsum, drowptr, nb, n2);
    k_rowptr<<<nb, TPB, 0, sc>>>(dhist, dbsum, drowptr, dcursor, ddinv, n2);
    k_permute2<<<g2E, TPB, 0, sc>>>(eraw, dcursor, dcsr, E, N);
    if (fork) cudaEventRecord(ev_join, s_side);

    // --- Main stream: W splits + conv1 GEMM (independent of CSR) ---
    k_wsplit<<<64, TPB>>>(W1, dwh, dwl);
    k_wsplit<<<64, TPB>>>(W2, dwh + CDIM * CDIM, dwl + CDIM * CDIM);
    k_gemm_mma<<<gGemm, TPB, GEMM_SMEM>>>(x_seq, dwh, dwl, b1, (__half*)dh, n2, 0);

    if (fork) cudaStreamWaitEvent(0, ev_join, 0);

    // conv1 aggregation, conv2 GEMM, conv2 aggregation (into d_out), importance.
    k_gather<0><<<gGath, TPB>>>(dh, dagg, drowptr, dcsr, ddinv, b1, n2);
    k_gemm_mma<<<gGemm, TPB, GEMM_SMEM>>>((const float*)dagg, dwh + CDIM * CDIM,
                                          dwl + CDIM * CDIM, b1, (__half*)dh, n2, 1);
    k_gather<1><<<gGath, TPB>>>(dh, (float4*)outs, drowptr, dcsr, ddinv, b2, n2);
    k_importance<<<(N * 32 + TPB - 1) / TPB, TPB>>>(outs + (size_t)(TT - 1) * N * CDIM,
                                                    Wc, bc, imp, N);
}